// round 7
// baseline (speedup 1.0000x reference)
#include <cuda_runtime.h>
#include <cuda_bf16.h>
#include <cstdint>

#define BATCH 4
#define SEQ   1024
#define DMODEL 1024
#define NHEAD 16
#define HDIM  64
#define PADV  (-1e7f)
#define LNEPS 1e-3f
#define NTOT  (BATCH*SEQ*DMODEL)   // 4194304
#define WTOT  (DMODEL*DMODEL)      // 1048576

// ---------------- scratch (device globals; no allocations) ----------------
__device__ __nv_bfloat16 g_Xh[3][NTOT];   // split inputs  (q,k,v)
__device__ __nv_bfloat16 g_Xl[3][NTOT];
__device__ __nv_bfloat16 g_Wh[3][WTOT];   // split weights
__device__ __nv_bfloat16 g_Wl[3][WTOT];
__device__ __nv_bfloat16 g_Ph[3][NTOT];   // projected Q,K,V (hi)
__device__ __nv_bfloat16 g_Pl[3][NTOT];   // projected Q,K,V (lo)
__device__ float g_O[NTOT];               // attention output (fp32)

// =================================================================
// helpers
// =================================================================
__device__ __forceinline__ uint32_t smem_u32(const void* p) {
    uint32_t a;
    asm("{ .reg .u64 t; cvta.to.shared.u64 t, %1; cvt.u32.u64 %0, t; }"
        : "=r"(a) : "l"(p));
    return a;
}

__device__ __forceinline__ void ldsm_x4(uint32_t* r, uint32_t addr) {
    asm volatile("ldmatrix.sync.aligned.m8n8.x4.shared.b16 {%0,%1,%2,%3}, [%4];"
                 : "=r"(r[0]), "=r"(r[1]), "=r"(r[2]), "=r"(r[3]) : "r"(addr));
}
__device__ __forceinline__ void ldsm_x4t(uint32_t* r, uint32_t addr) {
    asm volatile("ldmatrix.sync.aligned.m8n8.x4.trans.shared.b16 {%0,%1,%2,%3}, [%4];"
                 : "=r"(r[0]), "=r"(r[1]), "=r"(r[2]), "=r"(r[3]) : "r"(addr));
}
__device__ __forceinline__ void mma_bf16(float* d, const uint32_t* a, const uint32_t* b) {
    asm volatile(
        "mma.sync.aligned.m16n8k16.row.col.f32.bf16.bf16.f32 "
        "{%0,%1,%2,%3}, {%4,%5,%6,%7}, {%8,%9}, {%0,%1,%2,%3};"
        : "+f"(d[0]), "+f"(d[1]), "+f"(d[2]), "+f"(d[3])
        : "r"(a[0]), "r"(a[1]), "r"(a[2]), "r"(a[3]), "r"(b[0]), "r"(b[1]));
}

#define CP16(dst, src) \
    asm volatile("cp.async.cg.shared.global [%0], [%1], 16;" :: "r"(dst), "l"(src))
#define CP_COMMIT() asm volatile("cp.async.commit_group;" ::: "memory")
#define CP_WAIT(n)  asm volatile("cp.async.wait_group %0;" :: "n"(n) : "memory")

__device__ __forceinline__ uint32_t pack2(__nv_bfloat16 a, __nv_bfloat16 b) {
    return (uint32_t)__bfloat16_as_ushort(a) | ((uint32_t)__bfloat16_as_ushort(b) << 16);
}
__device__ __forceinline__ void split4(float4 v, uint2& hi, uint2& lo) {
    __nv_bfloat16 h0 = __float2bfloat16_rn(v.x);
    __nv_bfloat16 h1 = __float2bfloat16_rn(v.y);
    __nv_bfloat16 h2 = __float2bfloat16_rn(v.z);
    __nv_bfloat16 h3 = __float2bfloat16_rn(v.w);
    hi = make_uint2(pack2(h0, h1), pack2(h2, h3));
    lo = make_uint2(
        pack2(__float2bfloat16_rn(v.x - __bfloat162float(h0)),
              __float2bfloat16_rn(v.y - __bfloat162float(h1))),
        pack2(__float2bfloat16_rn(v.z - __bfloat162float(h2)),
              __float2bfloat16_rn(v.w - __bfloat162float(h3))));
}
// split a float pair into packed hi; return lo via out-param
__device__ __forceinline__ uint32_t splitpair(float x, float y, uint32_t& lo) {
    __nv_bfloat16 hx = __float2bfloat16_rn(x);
    __nv_bfloat16 hy = __float2bfloat16_rn(y);
    lo = pack2(__float2bfloat16_rn(x - __bfloat162float(hx)),
               __float2bfloat16_rn(y - __bfloat162float(hy)));
    return pack2(hx, hy);
}

// =================================================================
// Kernel 0: fused fp32 -> bf16 hi/lo preconversion for all 6 arrays.
// =================================================================
#define XB (NTOT / 1024)   // 4096
#define WB (WTOT / 1024)   // 1024

__global__ __launch_bounds__(256) void convert_all_kernel(
    const float* __restrict__ Xq, const float* __restrict__ Xk, const float* __restrict__ Xv,
    const float* __restrict__ Wq, const float* __restrict__ Wk, const float* __restrict__ Wv)
{
    int bid = blockIdx.x;
    const float* src;
    __nv_bfloat16 *hp, *lp;
    int off;
    if (bid < 3 * XB) {
        int job = bid / XB;
        off = (bid % XB) * 256 + threadIdx.x;
        src = (job == 0) ? Xq : (job == 1) ? Xk : Xv;
        hp = g_Xh[job];
        lp = g_Xl[job];
    } else {
        int r = bid - 3 * XB;
        int job = r / WB;
        off = (r % WB) * 256 + threadIdx.x;
        src = (job == 0) ? Wq : (job == 1) ? Wk : Wv;
        hp = g_Wh[job];
        lp = g_Wl[job];
    }
    float4 v = ((const float4*)src)[off];
    uint2 hi, lo;
    split4(v, hi, lo);
    ((uint2*)hp)[off] = hi;
    ((uint2*)lp)[off] = lo;
}

// =================================================================
// Kernel 1: QKV projections, mma.sync bf16 split-2, cp.async 3-stage.
// CTA tile 128x128, BK=32, 8 warps (2x4), warp tile 64x32.
// One __syncthreads per iteration (issue-after-sync ring discipline).
// =================================================================
#define PA 40      // A pitch (bf16): 80 B rows
#define PB 136     // B pitch (bf16): 272 B rows
#define PRJ_AH 0
#define PRJ_AL 10240
#define PRJ_BH 20480
#define PRJ_BL 29184
#define PRJ_STAGE 37888
#define PRJ_SMEM (3 * PRJ_STAGE)   // 113664

__global__ __launch_bounds__(256) void proj_mma_kernel()
{
    const int z = blockIdx.z;
    const __nv_bfloat16* Xh = g_Xh[z];
    const __nv_bfloat16* Xl = g_Xl[z];
    const __nv_bfloat16* Wh = g_Wh[z];
    const __nv_bfloat16* Wl = g_Wl[z];
    __nv_bfloat16* Ph = g_Ph[z];
    __nv_bfloat16* Pl = g_Pl[z];

    extern __shared__ char smem[];
    const uint32_t sb = smem_u32(smem);

    const int tid  = threadIdx.x;
    const int lane = tid & 31;
    const int wid  = tid >> 5;
    const int wm   = (wid >> 2) * 64;
    const int wn   = (wid & 3) * 32;
    const int rowBase = blockIdx.y * 128;
    const int colBase = blockIdx.x * 128;
    const int arow = lane & 15;
    const int acol = (lane >> 4) * 8;

    auto issue = [&](int it) {
        const uint32_t stb = sb + (uint32_t)(it % 3) * PRJ_STAGE;
        const int k0 = it * 32;
#pragma unroll
        for (int i = 0; i < 8; i++) {
            int idx = i * 256 + tid;
            if (idx < 1024) {                 // A tile: 128 rows x 32 k
                int half = idx >> 9;
                int j = idx & 511;
                int r = j >> 2, g = j & 3;
                const __nv_bfloat16* src =
                    (half ? Xl : Xh) + (size_t)(rowBase + r) * DMODEL + k0 + g * 8;
                CP16(stb + (half ? PRJ_AL : PRJ_AH) + r * 80 + g * 16, src);
            } else {                          // B tile: 32 k-rows x 128 n
                int j = idx - 1024;
                int half = j >> 9;
                j &= 511;
                int r = j >> 4, cc = j & 15;
                const __nv_bfloat16* src =
                    (half ? Wl : Wh) + (size_t)(k0 + r) * DMODEL + colBase + cc * 8;
                CP16(stb + (half ? PRJ_BL : PRJ_BH) + r * 272 + cc * 16, src);
            }
        }
        CP_COMMIT();
    };

    float acc[4][4][4];
#pragma unroll
    for (int i = 0; i < 4; i++)
#pragma unroll
        for (int j = 0; j < 4; j++)
#pragma unroll
            for (int u = 0; u < 4; u++) acc[i][j][u] = 0.0f;

    issue(0);
    issue(1);

    for (int it = 0; it < 32; ++it) {
        // groups in flight: it, it+1  -> wait until oldest (it) is done
        if (it < 31) { CP_WAIT(1); } else { CP_WAIT(0); }
        __syncthreads();
        // stage (it+2)%3 == stage consumed at it-1; the barrier above makes
        // refilling it safe without a trailing sync.
        if (it + 2 < 32) issue(it + 2);

        const uint32_t stb = sb + (uint32_t)(it % 3) * PRJ_STAGE;
#pragma unroll
        for (int kb = 0; kb < 32; kb += 16) {
            uint32_t ah[4][4], al[4][4];
#pragma unroll
            for (int mb = 0; mb < 4; mb++) {
                uint32_t off = (uint32_t)((wm + mb * 16 + arow) * PA + kb + acol) * 2;
                ldsm_x4(ah[mb], stb + PRJ_AH + off);
                ldsm_x4(al[mb], stb + PRJ_AL + off);
            }
            uint32_t bh[2][4], bl[2][4];
#pragma unroll
            for (int nb2 = 0; nb2 < 2; nb2++) {
                uint32_t off = (uint32_t)((kb + arow) * PB + wn + nb2 * 16 + acol) * 2;
                ldsm_x4t(bh[nb2], stb + PRJ_BH + off);
                ldsm_x4t(bl[nb2], stb + PRJ_BL + off);
            }
#pragma unroll
            for (int mb = 0; mb < 4; mb++)
#pragma unroll
                for (int nb = 0; nb < 4; nb++) {
                    const uint32_t* ph = &bh[nb >> 1][(nb & 1) * 2];
                    const uint32_t* pl = &bl[nb >> 1][(nb & 1) * 2];
                    mma_bf16(acc[mb][nb], ah[mb], ph);
                    mma_bf16(acc[mb][nb], al[mb], ph);
                    mma_bf16(acc[mb][nb], ah[mb], pl);
                }
        }
    }

    // epilogue: split fp32 acc into bf16 hi/lo and store
    const int grp = lane >> 2;
    const int qd  = lane & 3;
#pragma unroll
    for (int mb = 0; mb < 4; mb++) {
#pragma unroll
        for (int nb = 0; nb < 4; nb++) {
            size_t row = (size_t)(rowBase + wm + mb * 16 + grp);
            size_t col = (size_t)(colBase + wn + nb * 8 + qd * 2);
            uint32_t lo0, lo1;
            uint32_t hi0 = splitpair(acc[mb][nb][0], acc[mb][nb][1], lo0);
            uint32_t hi1 = splitpair(acc[mb][nb][2], acc[mb][nb][3], lo1);
            *(uint32_t*)&Ph[row * DMODEL + col] = hi0;
            *(uint32_t*)&Pl[row * DMODEL + col] = lo0;
            *(uint32_t*)&Ph[(row + 8) * DMODEL + col] = hi1;
            *(uint32_t*)&Pl[(row + 8) * DMODEL + col] = lo1;
        }
    }
}

// =================================================================
// Kernel 2: flash attention on mma.sync, bf16 split-2 throughout.
// CTA = (64 queries, head h, batch b); 4 warps x 16 query rows.
// K/V tiles (64 keys) cp.async double-buffered, 1 sync/iter,
// all key masks preloaded once.
// =================================================================
#define ATP 72              // smem pitch (bf16) for 64-wide tiles: 144 B rows
#define AT_KH 0
#define AT_KL 9216
#define AT_VH 18432
#define AT_VL 27648
#define AT_STAGE 36864
#define AT_KM (2 * AT_STAGE)            // int[1024] at byte 73728
#define AT_SMEM (AT_KM + 1024 * 4)      // 77824

__global__ __launch_bounds__(128) void attn_mma_kernel(
    const int* __restrict__ qmask, const int* __restrict__ kmask)
{
    extern __shared__ char smem[];
    const uint32_t sb = smem_u32(smem);
    int* sKm = (int*)(smem + AT_KM);

    const int tid  = threadIdx.x;
    const int lane = tid & 31;
    const int wid  = tid >> 5;
    const int grp  = lane >> 2;
    const int qc   = lane & 3;
    const int arow = lane & 15;
    const int acol = (lane >> 4) * 8;

    const int q0 = blockIdx.x * 64;
    const int h  = blockIdx.y;
    const int b  = blockIdx.z;
    const size_t rowB = (size_t)b * SEQ;
    const size_t hoff = (size_t)h * HDIM;

    const __nv_bfloat16* Qh = g_Ph[0];
    const __nv_bfloat16* Ql = g_Pl[0];
    const __nv_bfloat16* Kh = g_Ph[1];
    const __nv_bfloat16* Kl = g_Pl[1];
    const __nv_bfloat16* Vh = g_Ph[2];
    const __nv_bfloat16* Vl = g_Pl[2];

    auto issue = [&](int it) {
        const int s = it & 1;
        const int k0 = it * 64;
        const uint32_t stb = sb + (uint32_t)s * AT_STAGE;
#pragma unroll
        for (int i = 0; i < 16; i++) {
            int idx = i * 128 + tid;          // 0..2047
            int arr = idx >> 9;
            int rem = idx & 511;
            int r = rem >> 3, cc = rem & 7;
            const __nv_bfloat16* base =
                (arr == 0) ? Kh : (arr == 1) ? Kl : (arr == 2) ? Vh : Vl;
            const __nv_bfloat16* src = base + (rowB + k0 + r) * DMODEL + hoff + cc * 8;
            CP16(stb + (uint32_t)arr * 9216 + r * 144 + cc * 16, src);
        }
        CP_COMMIT();
    };

    issue(0);

    // ---- preload the full key-mask row (all 16 tiles) ----
#pragma unroll
    for (int i = 0; i < 8; i++)
        sKm[i * 128 + tid] = kmask[rowB + i * 128 + tid];

    // ---- Q fragments straight from global (hi/lo), register-resident ----
    const int gq0 = q0 + wid * 16 + grp;      // global query row (and +8)
    uint32_t qfh[4][4], qfl[4][4];
    {
        const size_t r0 = (rowB + gq0) * DMODEL + hoff + 2 * qc;
#pragma unroll
        for (int kb = 0; kb < 4; kb++) {
            size_t base = r0 + kb * 16;
            qfh[kb][0] = *(const uint32_t*)&Qh[base];
            qfh[kb][1] = *(const uint32_t*)&Qh[base + 8 * DMODEL];
            qfh[kb][2] = *(const uint32_t*)&Qh[base + 8];
            qfh[kb][3] = *(const uint32_t*)&Qh[base + 8 * DMODEL + 8];
            qfl[kb][0] = *(const uint32_t*)&Ql[base];
            qfl[kb][1] = *(const uint32_t*)&Ql[base + 8 * DMODEL];
            qfl[kb][2] = *(const uint32_t*)&Ql[base + 8];
            qfl[kb][3] = *(const uint32_t*)&Ql[base + 8 * DMODEL + 8];
        }
    }

    float out[8][4];
#pragma unroll
    for (int nb = 0; nb < 8; nb++)
#pragma unroll
        for (int u = 0; u < 4; u++) out[nb][u] = 0.0f;
    float m0 = -1e30f, m1 = -1e30f, l0 = 0.0f, l1 = 0.0f;

    __syncthreads();   // sKm visible to all

    for (int it = 0; it < SEQ / 64; ++it) {
        CP_WAIT(0);
        __syncthreads();
        // stage (it+1)&1 was consumed at it-1; barrier above makes refill safe
        if (it + 1 < 16) issue(it + 1);

        const uint32_t stb = sb + (uint32_t)(it & 1) * AT_STAGE;
        const int* km = &sKm[it * 64];

        // ---- scores S = Q K^T ----
        float sc[8][4];
#pragma unroll
        for (int nb = 0; nb < 8; nb++)
#pragma unroll
            for (int u = 0; u < 4; u++) sc[nb][u] = 0.0f;

#pragma unroll
        for (int kb = 0; kb < 4; kb++) {
            uint32_t bkh[4][4], bkl[4][4];
#pragma unroll
            for (int nb2 = 0; nb2 < 4; nb2++) {
                uint32_t off = (uint32_t)((nb2 * 16 + arow) * ATP + kb * 16 + acol) * 2;
                ldsm_x4(bkh[nb2], stb + AT_KH + off);   // K stored [key][d]: non-trans
                ldsm_x4(bkl[nb2], stb + AT_KL + off);
            }
#pragma unroll
            for (int nb = 0; nb < 8; nb++) {
                int g2 = nb >> 1, sub = nb & 1;
                uint32_t bh[2] = {bkh[g2][sub], bkh[g2][sub + 2]};
                uint32_t bl[2] = {bkl[g2][sub], bkl[g2][sub + 2]};
                mma_bf16(sc[nb], qfh[kb], bh);
                mma_bf16(sc[nb], qfl[kb], bh);
                mma_bf16(sc[nb], qfh[kb], bl);
            }
        }

        // ---- scale + key mask ----
#pragma unroll
        for (int nb = 0; nb < 8; nb++) {
            int c0 = nb * 8 + 2 * qc;
            int k0m = km[c0], k1m = km[c0 + 1];
            sc[nb][0] = k0m ? sc[nb][0] * 0.125f : PADV;
            sc[nb][1] = k1m ? sc[nb][1] * 0.125f : PADV;
            sc[nb][2] = k0m ? sc[nb][2] * 0.125f : PADV;
            sc[nb][3] = k1m ? sc[nb][3] * 0.125f : PADV;
        }

        // ---- online softmax (rows gq0 and gq0+8) ----
        float mx0 = -1e30f, mx1 = -1e30f;
#pragma unroll
        for (int nb = 0; nb < 8; nb++) {
            mx0 = fmaxf(mx0, fmaxf(sc[nb][0], sc[nb][1]));
            mx1 = fmaxf(mx1, fmaxf(sc[nb][2], sc[nb][3]));
        }
        mx0 = fmaxf(mx0, __shfl_xor_sync(0xffffffffu, mx0, 1));
        mx0 = fmaxf(mx0, __shfl_xor_sync(0xffffffffu, mx0, 2));
        mx1 = fmaxf(mx1, __shfl_xor_sync(0xffffffffu, mx1, 1));
        mx1 = fmaxf(mx1, __shfl_xor_sync(0xffffffffu, mx1, 2));
        float mn0 = fmaxf(m0, mx0), mn1 = fmaxf(m1, mx1);
        float a0 = __expf(m0 - mn0), a1 = __expf(m1 - mn1);
        float rs0 = 0.0f, rs1 = 0.0f;
#pragma unroll
        for (int nb = 0; nb < 8; nb++) {
            sc[nb][0] = __expf(sc[nb][0] - mn0); rs0 += sc[nb][0];
            sc[nb][1] = __expf(sc[nb][1] - mn0); rs0 += sc[nb][1];
            sc[nb][2] = __expf(sc[nb][2] - mn1); rs1 += sc[nb][2];
            sc[nb][3] = __expf(sc[nb][3] - mn1); rs1 += sc[nb][3];
        }
        rs0 += __shfl_xor_sync(0xffffffffu, rs0, 1);
        rs0 += __shfl_xor_sync(0xffffffffu, rs0, 2);
        rs1 += __shfl_xor_sync(0xffffffffu, rs1, 1);
        rs1 += __shfl_xor_sync(0xffffffffu, rs1, 2);
        l0 = l0 * a0 + rs0;
        l1 = l1 * a1 + rs1;
        m0 = mn0;
        m1 = mn1;
#pragma unroll
        for (int nb = 0; nb < 8; nb++) {
            out[nb][0] *= a0; out[nb][1] *= a0;
            out[nb][2] *= a1; out[nb][3] *= a1;
        }

        // ---- O += P V : repack P C-frags -> bf16 A-frags in-register ----
#pragma unroll
        for (int kb = 0; kb < 4; kb++) {
            uint32_t pah[4], pal[4];
            pah[0] = splitpair(sc[2 * kb][0],     sc[2 * kb][1],     pal[0]);
            pah[1] = splitpair(sc[2 * kb][2],     sc[2 * kb][3],     pal[1]);
            pah[2] = splitpair(sc[2 * kb + 1][0], sc[2 * kb + 1][1], pal[2]);
            pah[3] = splitpair(sc[2 * kb + 1][2], sc[2 * kb + 1][3], pal[3]);

            uint32_t bvh[4][4], bvl[4][4];
#pragma unroll
            for (int nb2 = 0; nb2 < 4; nb2++) {
                uint32_t off = (uint32_t)((kb * 16 + arow) * ATP + nb2 * 16 + acol) * 2;
                ldsm_x4t(bvh[nb2], stb + AT_VH + off);   // V stored [key][d]: trans
                ldsm_x4t(bvl[nb2], stb + AT_VL + off);
            }
#pragma unroll
            for (int nb = 0; nb < 8; nb++) {
                int g2 = nb >> 1, sub = nb & 1;
                const uint32_t* bh = &bvh[g2][2 * sub];
                const uint32_t* bl = &bvl[g2][2 * sub];
                mma_bf16(out[nb], pah, bh);
                mma_bf16(out[nb], pal, bh);
                mma_bf16(out[nb], pah, bl);
            }
        }
    }

    // ---- finalize: 1/l, query mask, fp32 store ----
    float s0 = (float)qmask[rowB + gq0]     / l0;
    float s1 = (float)qmask[rowB + gq0 + 8] / l1;
#pragma unroll
    for (int nb = 0; nb < 8; nb++) {
        size_t col = hoff + nb * 8 + 2 * qc;
        *(float2*)&g_O[(rowB + gq0) * DMODEL + col] =
            make_float2(out[nb][0] * s0, out[nb][1] * s0);
        *(float2*)&g_O[(rowB + gq0 + 8) * DMODEL + col] =
            make_float2(out[nb][2] * s1, out[nb][3] * s1);
    }
}

// =================================================================
// Kernel 3: residual + LayerNorm per row (unchanged)
// =================================================================
__device__ __forceinline__ float block_sum256(float v, float* red)
{
#pragma unroll
    for (int off = 16; off; off >>= 1)
        v += __shfl_xor_sync(0xffffffffu, v, off);
    if ((threadIdx.x & 31) == 0) red[threadIdx.x >> 5] = v;
    __syncthreads();
    float tot = 0.0f;
#pragma unroll
    for (int w = 0; w < 8; w++) tot += red[w];
    __syncthreads();
    return tot;
}

__global__ __launch_bounds__(256) void ln_kernel(
    const float* __restrict__ queries,
    const float* __restrict__ gamma,
    const float* __restrict__ beta,
    float* __restrict__ out)
{
    __shared__ float red[8];
    const int row = blockIdx.x;
    const int t   = threadIdx.x;
    const size_t base = (size_t)row * DMODEL + t * 4;

    float4 a = *(const float4*)&queries[base];
    float4 b = *(const float4*)&g_O[base];
    float x[4] = {a.x + b.x, a.y + b.y, a.z + b.z, a.w + b.w};

    float s = x[0] + x[1] + x[2] + x[3];
    s = block_sum256(s, red);
    float mean = s * (1.0f / DMODEL);

    float d[4] = {x[0] - mean, x[1] - mean, x[2] - mean, x[3] - mean};
    float ss = d[0] * d[0] + d[1] * d[1] + d[2] * d[2] + d[3] * d[3];
    ss = block_sum256(ss, red);
    float rstd = rsqrtf(ss * (1.0f / DMODEL) + LNEPS);

    float4 g  = *(const float4*)&gamma[t * 4];
    float4 be = *(const float4*)&beta[t * 4];
    float4 y = make_float4(g.x * d[0] * rstd + be.x,
                           g.y * d[1] * rstd + be.y,
                           g.z * d[2] * rstd + be.z,
                           g.w * d[3] * rstd + be.w);
    *(float4*)&out[base] = y;
}

// =================================================================
extern "C" void kernel_launch(void* const* d_in, const int* in_sizes, int n_in,
                              void* d_out, int out_size)
{
    const float* queries = (const float*)d_in[0];
    const float* keys    = (const float*)d_in[1];
    const float* values  = (const float*)d_in[2];
    const int*   qmask   = (const int*)d_in[3];
    const int*   kmask   = (const int*)d_in[4];
    const float* Wq      = (const float*)d_in[5];
    const float* Wk      = (const float*)d_in[6];
    const float* Wv      = (const float*)d_in[7];
    const float* gamma   = (const float*)d_in[8];
    const float* beta    = (const float*)d_in[9];
    float* out = (float*)d_out;

    cudaFuncSetAttribute(proj_mma_kernel,
                         cudaFuncAttributeMaxDynamicSharedMemorySize, PRJ_SMEM);
    cudaFuncSetAttribute(attn_mma_kernel,
                         cudaFuncAttributeMaxDynamicSharedMemorySize, AT_SMEM);

    convert_all_kernel<<<3 * XB + 3 * WB, 256>>>(queries, keys, values, Wq, Wk, Wv);

    proj_mma_kernel<<<dim3(DMODEL / 128, (BATCH * SEQ) / 128, 3), 256, PRJ_SMEM>>>();

    attn_mma_kernel<<<dim3(SEQ / 64, NHEAD, BATCH), 128, AT_SMEM>>>(qmask, kmask);

    ln_kernel<<<BATCH * SEQ, 256>>>(queries, gamma, beta, out);
}

// round 8
// speedup vs baseline: 1.0067x; 1.0067x over previous
#include <cuda_runtime.h>
#include <cuda_bf16.h>
#include <cstdint>

#define BATCH 4
#define SEQ   1024
#define DMODEL 1024
#define NHEAD 16
#define HDIM  64
#define PADV  (-1e7f)
#define LNEPS 1e-3f
#define NTOT  (BATCH*SEQ*DMODEL)   // 4194304
#define WTOT  (DMODEL*DMODEL)      // 1048576

// ---------------- scratch (device globals; no allocations) ----------------
__device__ __nv_bfloat16 g_Xh[3][NTOT];   // split inputs  (q,k,v)
__device__ __nv_bfloat16 g_Xl[3][NTOT];
__device__ __nv_bfloat16 g_Wh[3][WTOT];   // split weights
__device__ __nv_bfloat16 g_Wl[3][WTOT];
__device__ __nv_bfloat16 g_Ph[3][NTOT];   // projected Q,K,V (hi)
__device__ __nv_bfloat16 g_Pl[3][NTOT];   // projected Q,K,V (lo)
__device__ float g_O[NTOT];               // attention output (fp32)

// =================================================================
// helpers
// =================================================================
__device__ __forceinline__ uint32_t smem_u32(const void* p) {
    uint32_t a;
    asm("{ .reg .u64 t; cvta.to.shared.u64 t, %1; cvt.u32.u64 %0, t; }"
        : "=r"(a) : "l"(p));
    return a;
}

__device__ __forceinline__ void ldsm_x4(uint32_t* r, uint32_t addr) {
    asm volatile("ldmatrix.sync.aligned.m8n8.x4.shared.b16 {%0,%1,%2,%3}, [%4];"
                 : "=r"(r[0]), "=r"(r[1]), "=r"(r[2]), "=r"(r[3]) : "r"(addr));
}
__device__ __forceinline__ void ldsm_x4t(uint32_t* r, uint32_t addr) {
    asm volatile("ldmatrix.sync.aligned.m8n8.x4.trans.shared.b16 {%0,%1,%2,%3}, [%4];"
                 : "=r"(r[0]), "=r"(r[1]), "=r"(r[2]), "=r"(r[3]) : "r"(addr));
}
__device__ __forceinline__ void mma_bf16(float* d, const uint32_t* a, const uint32_t* b) {
    asm volatile(
        "mma.sync.aligned.m16n8k16.row.col.f32.bf16.bf16.f32 "
        "{%0,%1,%2,%3}, {%4,%5,%6,%7}, {%8,%9}, {%0,%1,%2,%3};"
        : "+f"(d[0]), "+f"(d[1]), "+f"(d[2]), "+f"(d[3])
        : "r"(a[0]), "r"(a[1]), "r"(a[2]), "r"(a[3]), "r"(b[0]), "r"(b[1]));
}

#define CP16(dst, src) \
    asm volatile("cp.async.cg.shared.global [%0], [%1], 16;" :: "r"(dst), "l"(src))
#define CP_COMMIT() asm volatile("cp.async.commit_group;" ::: "memory")
#define CP_WAIT(n)  asm volatile("cp.async.wait_group %0;" :: "n"(n) : "memory")

__device__ __forceinline__ uint32_t pack2(__nv_bfloat16 a, __nv_bfloat16 b) {
    return (uint32_t)__bfloat16_as_ushort(a) | ((uint32_t)__bfloat16_as_ushort(b) << 16);
}
__device__ __forceinline__ void split4(float4 v, uint2& hi, uint2& lo) {
    __nv_bfloat16 h0 = __float2bfloat16_rn(v.x);
    __nv_bfloat16 h1 = __float2bfloat16_rn(v.y);
    __nv_bfloat16 h2 = __float2bfloat16_rn(v.z);
    __nv_bfloat16 h3 = __float2bfloat16_rn(v.w);
    hi = make_uint2(pack2(h0, h1), pack2(h2, h3));
    lo = make_uint2(
        pack2(__float2bfloat16_rn(v.x - __bfloat162float(h0)),
              __float2bfloat16_rn(v.y - __bfloat162float(h1))),
        pack2(__float2bfloat16_rn(v.z - __bfloat162float(h2)),
              __float2bfloat16_rn(v.w - __bfloat162float(h3))));
}
// split a float pair into packed hi; return lo via out-param
__device__ __forceinline__ uint32_t splitpair(float x, float y, uint32_t& lo) {
    __nv_bfloat16 hx = __float2bfloat16_rn(x);
    __nv_bfloat16 hy = __float2bfloat16_rn(y);
    lo = pack2(__float2bfloat16_rn(x - __bfloat162float(hx)),
               __float2bfloat16_rn(y - __bfloat162float(hy)));
    return pack2(hx, hy);
}

// =================================================================
// Kernel 0: fused fp32 -> bf16 hi/lo preconversion for all 6 arrays.
// =================================================================
#define XB (NTOT / 1024)   // 4096
#define WB (WTOT / 1024)   // 1024

__global__ __launch_bounds__(256) void convert_all_kernel(
    const float* __restrict__ Xq, const float* __restrict__ Xk, const float* __restrict__ Xv,
    const float* __restrict__ Wq, const float* __restrict__ Wk, const float* __restrict__ Wv)
{
    int bid = blockIdx.x;
    const float* src;
    __nv_bfloat16 *hp, *lp;
    int off;
    if (bid < 3 * XB) {
        int job = bid / XB;
        off = (bid % XB) * 256 + threadIdx.x;
        src = (job == 0) ? Xq : (job == 1) ? Xk : Xv;
        hp = g_Xh[job];
        lp = g_Xl[job];
    } else {
        int r = bid - 3 * XB;
        int job = r / WB;
        off = (r % WB) * 256 + threadIdx.x;
        src = (job == 0) ? Wq : (job == 1) ? Wk : Wv;
        hp = g_Wh[job];
        lp = g_Wl[job];
    }
    float4 v = ((const float4*)src)[off];
    uint2 hi, lo;
    split4(v, hi, lo);
    ((uint2*)hp)[off] = hi;
    ((uint2*)lp)[off] = lo;
}

// =================================================================
// Kernel 1: QKV projections, mma.sync bf16 split-2, cp.async 2-stage,
// ONE __syncthreads per iteration (issue-after-sync; single group in
// flight, so CP_WAIT(0)+barrier proves the refill target is idle).
// CTA tile 128x128, BK=32, 8 warps (2x4), warp tile 64x32.
// =================================================================
#define PA 40      // A pitch (bf16): 80 B rows
#define PB 136     // B pitch (bf16): 272 B rows
#define PRJ_AH 0
#define PRJ_AL 10240
#define PRJ_BH 20480
#define PRJ_BL 29184
#define PRJ_STAGE 37888
#define PRJ_SMEM (2 * PRJ_STAGE)   // 75776 -> up to 3 CTAs/SM

__global__ __launch_bounds__(256) void proj_mma_kernel()
{
    const int z = blockIdx.z;
    const __nv_bfloat16* Xh = g_Xh[z];
    const __nv_bfloat16* Xl = g_Xl[z];
    const __nv_bfloat16* Wh = g_Wh[z];
    const __nv_bfloat16* Wl = g_Wl[z];
    __nv_bfloat16* Ph = g_Ph[z];
    __nv_bfloat16* Pl = g_Pl[z];

    extern __shared__ char smem[];
    const uint32_t sb = smem_u32(smem);

    const int tid  = threadIdx.x;
    const int lane = tid & 31;
    const int wid  = tid >> 5;
    const int wm   = (wid >> 2) * 64;
    const int wn   = (wid & 3) * 32;
    const int rowBase = blockIdx.y * 128;
    const int colBase = blockIdx.x * 128;
    const int arow = lane & 15;
    const int acol = (lane >> 4) * 8;

    auto issue = [&](int it) {
        const uint32_t stb = sb + (uint32_t)(it & 1) * PRJ_STAGE;
        const int k0 = it * 32;
#pragma unroll
        for (int i = 0; i < 8; i++) {
            int idx = i * 256 + tid;
            if (idx < 1024) {                 // A tile: 128 rows x 32 k
                int half = idx >> 9;
                int j = idx & 511;
                int r = j >> 2, g = j & 3;
                const __nv_bfloat16* src =
                    (half ? Xl : Xh) + (size_t)(rowBase + r) * DMODEL + k0 + g * 8;
                CP16(stb + (half ? PRJ_AL : PRJ_AH) + r * 80 + g * 16, src);
            } else {                          // B tile: 32 k-rows x 128 n
                int j = idx - 1024;
                int half = j >> 9;
                j &= 511;
                int r = j >> 4, cc = j & 15;
                const __nv_bfloat16* src =
                    (half ? Wl : Wh) + (size_t)(k0 + r) * DMODEL + colBase + cc * 8;
                CP16(stb + (half ? PRJ_BL : PRJ_BH) + r * 272 + cc * 16, src);
            }
        }
        CP_COMMIT();
    };

    float acc[4][4][4];
#pragma unroll
    for (int i = 0; i < 4; i++)
#pragma unroll
        for (int j = 0; j < 4; j++)
#pragma unroll
            for (int u = 0; u < 4; u++) acc[i][j][u] = 0.0f;

    issue(0);

    for (int it = 0; it < 32; ++it) {
        CP_WAIT(0);          // single group in flight: data for stage it ready
        __syncthreads();     // all warps done with stage it-1 (= refill target)
        if (it + 1 < 32) issue(it + 1);   // overlaps compute below

        const uint32_t stb = sb + (uint32_t)(it & 1) * PRJ_STAGE;
#pragma unroll
        for (int kb = 0; kb < 32; kb += 16) {
            uint32_t ah[4][4], al[4][4];
#pragma unroll
            for (int mb = 0; mb < 4; mb++) {
                uint32_t off = (uint32_t)((wm + mb * 16 + arow) * PA + kb + acol) * 2;
                ldsm_x4(ah[mb], stb + PRJ_AH + off);
                ldsm_x4(al[mb], stb + PRJ_AL + off);
            }
            uint32_t bh[2][4], bl[2][4];
#pragma unroll
            for (int nb2 = 0; nb2 < 2; nb2++) {
                uint32_t off = (uint32_t)((kb + arow) * PB + wn + nb2 * 16 + acol) * 2;
                ldsm_x4t(bh[nb2], stb + PRJ_BH + off);
                ldsm_x4t(bl[nb2], stb + PRJ_BL + off);
            }
#pragma unroll
            for (int mb = 0; mb < 4; mb++)
#pragma unroll
                for (int nb = 0; nb < 4; nb++) {
                    const uint32_t* ph = &bh[nb >> 1][(nb & 1) * 2];
                    const uint32_t* pl = &bl[nb >> 1][(nb & 1) * 2];
                    mma_bf16(acc[mb][nb], ah[mb], ph);
                    mma_bf16(acc[mb][nb], al[mb], ph);
                    mma_bf16(acc[mb][nb], ah[mb], pl);
                }
        }
    }

    // epilogue: split fp32 acc into bf16 hi/lo and store
    const int grp = lane >> 2;
    const int qd  = lane & 3;
#pragma unroll
    for (int mb = 0; mb < 4; mb++) {
#pragma unroll
        for (int nb = 0; nb < 4; nb++) {
            size_t row = (size_t)(rowBase + wm + mb * 16 + grp);
            size_t col = (size_t)(colBase + wn + nb * 8 + qd * 2);
            uint32_t lo0, lo1;
            uint32_t hi0 = splitpair(acc[mb][nb][0], acc[mb][nb][1], lo0);
            uint32_t hi1 = splitpair(acc[mb][nb][2], acc[mb][nb][3], lo1);
            *(uint32_t*)&Ph[row * DMODEL + col] = hi0;
            *(uint32_t*)&Pl[row * DMODEL + col] = lo0;
            *(uint32_t*)&Ph[(row + 8) * DMODEL + col] = hi1;
            *(uint32_t*)&Pl[(row + 8) * DMODEL + col] = lo1;
        }
    }
}

// =================================================================
// Kernel 2: flash attention on mma.sync, bf16 split-2 throughout.
// CTA = (64 queries, head h, batch b); 4 warps x 16 query rows.
// K/V tiles (64 keys) cp.async double-buffered, 1 sync/iter,
// all key masks preloaded once.  (R7 form — kept)
// =================================================================
#define ATP 72              // smem pitch (bf16) for 64-wide tiles: 144 B rows
#define AT_KH 0
#define AT_KL 9216
#define AT_VH 18432
#define AT_VL 27648
#define AT_STAGE 36864
#define AT_KM (2 * AT_STAGE)            // int[1024] at byte 73728
#define AT_SMEM (AT_KM + 1024 * 4)      // 77824

__global__ __launch_bounds__(128) void attn_mma_kernel(
    const int* __restrict__ qmask, const int* __restrict__ kmask)
{
    extern __shared__ char smem[];
    const uint32_t sb = smem_u32(smem);
    int* sKm = (int*)(smem + AT_KM);

    const int tid  = threadIdx.x;
    const int lane = tid & 31;
    const int wid  = tid >> 5;
    const int grp  = lane >> 2;
    const int qc   = lane & 3;
    const int arow = lane & 15;
    const int acol = (lane >> 4) * 8;

    const int q0 = blockIdx.x * 64;
    const int h  = blockIdx.y;
    const int b  = blockIdx.z;
    const size_t rowB = (size_t)b * SEQ;
    const size_t hoff = (size_t)h * HDIM;

    const __nv_bfloat16* Qh = g_Ph[0];
    const __nv_bfloat16* Ql = g_Pl[0];
    const __nv_bfloat16* Kh = g_Ph[1];
    const __nv_bfloat16* Kl = g_Pl[1];
    const __nv_bfloat16* Vh = g_Ph[2];
    const __nv_bfloat16* Vl = g_Pl[2];

    auto issue = [&](int it) {
        const int s = it & 1;
        const int k0 = it * 64;
        const uint32_t stb = sb + (uint32_t)s * AT_STAGE;
#pragma unroll
        for (int i = 0; i < 16; i++) {
            int idx = i * 128 + tid;          // 0..2047
            int arr = idx >> 9;
            int rem = idx & 511;
            int r = rem >> 3, cc = rem & 7;
            const __nv_bfloat16* base =
                (arr == 0) ? Kh : (arr == 1) ? Kl : (arr == 2) ? Vh : Vl;
            const __nv_bfloat16* src = base + (rowB + k0 + r) * DMODEL + hoff + cc * 8;
            CP16(stb + (uint32_t)arr * 9216 + r * 144 + cc * 16, src);
        }
        CP_COMMIT();
    };

    issue(0);

    // ---- preload the full key-mask row (all 16 tiles) ----
#pragma unroll
    for (int i = 0; i < 8; i++)
        sKm[i * 128 + tid] = kmask[rowB + i * 128 + tid];

    // ---- Q fragments straight from global (hi/lo), register-resident ----
    const int gq0 = q0 + wid * 16 + grp;      // global query row (and +8)
    uint32_t qfh[4][4], qfl[4][4];
    {
        const size_t r0 = (rowB + gq0) * DMODEL + hoff + 2 * qc;
#pragma unroll
        for (int kb = 0; kb < 4; kb++) {
            size_t base = r0 + kb * 16;
            qfh[kb][0] = *(const uint32_t*)&Qh[base];
            qfh[kb][1] = *(const uint32_t*)&Qh[base + 8 * DMODEL];
            qfh[kb][2] = *(const uint32_t*)&Qh[base + 8];
            qfh[kb][3] = *(const uint32_t*)&Qh[base + 8 * DMODEL + 8];
            qfl[kb][0] = *(const uint32_t*)&Ql[base];
            qfl[kb][1] = *(const uint32_t*)&Ql[base + 8 * DMODEL];
            qfl[kb][2] = *(const uint32_t*)&Ql[base + 8];
            qfl[kb][3] = *(const uint32_t*)&Ql[base + 8 * DMODEL + 8];
        }
    }

    float out[8][4];
#pragma unroll
    for (int nb = 0; nb < 8; nb++)
#pragma unroll
        for (int u = 0; u < 4; u++) out[nb][u] = 0.0f;
    float m0 = -1e30f, m1 = -1e30f, l0 = 0.0f, l1 = 0.0f;

    __syncthreads();   // sKm visible to all

    for (int it = 0; it < SEQ / 64; ++it) {
        CP_WAIT(0);
        __syncthreads();
        // stage (it+1)&1 was consumed at it-1; barrier above makes refill safe
        if (it + 1 < 16) issue(it + 1);

        const uint32_t stb = sb + (uint32_t)(it & 1) * AT_STAGE;
        const int* km = &sKm[it * 64];

        // ---- scores S = Q K^T ----
        float sc[8][4];
#pragma unroll
        for (int nb = 0; nb < 8; nb++)
#pragma unroll
            for (int u = 0; u < 4; u++) sc[nb][u] = 0.0f;

#pragma unroll
        for (int kb = 0; kb < 4; kb++) {
            uint32_t bkh[4][4], bkl[4][4];
#pragma unroll
            for (int nb2 = 0; nb2 < 4; nb2++) {
                uint32_t off = (uint32_t)((nb2 * 16 + arow) * ATP + kb * 16 + acol) * 2;
                ldsm_x4(bkh[nb2], stb + AT_KH + off);   // K stored [key][d]: non-trans
                ldsm_x4(bkl[nb2], stb + AT_KL + off);
            }
#pragma unroll
            for (int nb = 0; nb < 8; nb++) {
                int g2 = nb >> 1, sub = nb & 1;
                uint32_t bh[2] = {bkh[g2][sub], bkh[g2][sub + 2]};
                uint32_t bl[2] = {bkl[g2][sub], bkl[g2][sub + 2]};
                mma_bf16(sc[nb], qfh[kb], bh);
                mma_bf16(sc[nb], qfl[kb], bh);
                mma_bf16(sc[nb], qfh[kb], bl);
            }
        }

        // ---- scale + key mask ----
#pragma unroll
        for (int nb = 0; nb < 8; nb++) {
            int c0 = nb * 8 + 2 * qc;
            int k0m = km[c0], k1m = km[c0 + 1];
            sc[nb][0] = k0m ? sc[nb][0] * 0.125f : PADV;
            sc[nb][1] = k1m ? sc[nb][1] * 0.125f : PADV;
            sc[nb][2] = k0m ? sc[nb][2] * 0.125f : PADV;
            sc[nb][3] = k1m ? sc[nb][3] * 0.125f : PADV;
        }

        // ---- online softmax (rows gq0 and gq0+8) ----
        float mx0 = -1e30f, mx1 = -1e30f;
#pragma unroll
        for (int nb = 0; nb < 8; nb++) {
            mx0 = fmaxf(mx0, fmaxf(sc[nb][0], sc[nb][1]));
            mx1 = fmaxf(mx1, fmaxf(sc[nb][2], sc[nb][3]));
        }
        mx0 = fmaxf(mx0, __shfl_xor_sync(0xffffffffu, mx0, 1));
        mx0 = fmaxf(mx0, __shfl_xor_sync(0xffffffffu, mx0, 2));
        mx1 = fmaxf(mx1, __shfl_xor_sync(0xffffffffu, mx1, 1));
        mx1 = fmaxf(mx1, __shfl_xor_sync(0xffffffffu, mx1, 2));
        float mn0 = fmaxf(m0, mx0), mn1 = fmaxf(m1, mx1);
        float a0 = __expf(m0 - mn0), a1 = __expf(m1 - mn1);
        float rs0 = 0.0f, rs1 = 0.0f;
#pragma unroll
        for (int nb = 0; nb < 8; nb++) {
            sc[nb][0] = __expf(sc[nb][0] - mn0); rs0 += sc[nb][0];
            sc[nb][1] = __expf(sc[nb][1] - mn0); rs0 += sc[nb][1];
            sc[nb][2] = __expf(sc[nb][2] - mn1); rs1 += sc[nb][2];
            sc[nb][3] = __expf(sc[nb][3] - mn1); rs1 += sc[nb][3];
        }
        rs0 += __shfl_xor_sync(0xffffffffu, rs0, 1);
        rs0 += __shfl_xor_sync(0xffffffffu, rs0, 2);
        rs1 += __shfl_xor_sync(0xffffffffu, rs1, 1);
        rs1 += __shfl_xor_sync(0xffffffffu, rs1, 2);
        l0 = l0 * a0 + rs0;
        l1 = l1 * a1 + rs1;
        m0 = mn0;
        m1 = mn1;
#pragma unroll
        for (int nb = 0; nb < 8; nb++) {
            out[nb][0] *= a0; out[nb][1] *= a0;
            out[nb][2] *= a1; out[nb][3] *= a1;
        }

        // ---- O += P V : repack P C-frags -> bf16 A-frags in-register ----
#pragma unroll
        for (int kb = 0; kb < 4; kb++) {
            uint32_t pah[4], pal[4];
            pah[0] = splitpair(sc[2 * kb][0],     sc[2 * kb][1],     pal[0]);
            pah[1] = splitpair(sc[2 * kb][2],     sc[2 * kb][3],     pal[1]);
            pah[2] = splitpair(sc[2 * kb + 1][0], sc[2 * kb + 1][1], pal[2]);
            pah[3] = splitpair(sc[2 * kb + 1][2], sc[2 * kb + 1][3], pal[3]);

            uint32_t bvh[4][4], bvl[4][4];
#pragma unroll
            for (int nb2 = 0; nb2 < 4; nb2++) {
                uint32_t off = (uint32_t)((kb * 16 + arow) * ATP + nb2 * 16 + acol) * 2;
                ldsm_x4t(bvh[nb2], stb + AT_VH + off);   // V stored [key][d]: trans
                ldsm_x4t(bvl[nb2], stb + AT_VL + off);
            }
#pragma unroll
            for (int nb = 0; nb < 8; nb++) {
                int g2 = nb >> 1, sub = nb & 1;
                const uint32_t* bh = &bvh[g2][2 * sub];
                const uint32_t* bl = &bvl[g2][2 * sub];
                mma_bf16(out[nb], pah, bh);
                mma_bf16(out[nb], pal, bh);
                mma_bf16(out[nb], pah, bl);
            }
        }
    }

    // ---- finalize: 1/l, query mask, fp32 store ----
    float s0 = (float)qmask[rowB + gq0]     / l0;
    float s1 = (float)qmask[rowB + gq0 + 8] / l1;
#pragma unroll
    for (int nb = 0; nb < 8; nb++) {
        size_t col = hoff + nb * 8 + 2 * qc;
        *(float2*)&g_O[(rowB + gq0) * DMODEL + col] =
            make_float2(out[nb][0] * s0, out[nb][1] * s0);
        *(float2*)&g_O[(rowB + gq0 + 8) * DMODEL + col] =
            make_float2(out[nb][2] * s1, out[nb][3] * s1);
    }
}

// =================================================================
// Kernel 3: residual + LayerNorm per row (unchanged)
// =================================================================
__device__ __forceinline__ float block_sum256(float v, float* red)
{
#pragma unroll
    for (int off = 16; off; off >>= 1)
        v += __shfl_xor_sync(0xffffffffu, v, off);
    if ((threadIdx.x & 31) == 0) red[threadIdx.x >> 5] = v;
    __syncthreads();
    float tot = 0.0f;
#pragma unroll
    for (int w = 0; w < 8; w++) tot += red[w];
    __syncthreads();
    return tot;
}

__global__ __launch_bounds__(256) void ln_kernel(
    const float* __restrict__ queries,
    const float* __restrict__ gamma,
    const float* __restrict__ beta,
    float* __restrict__ out)
{
    __shared__ float red[8];
    const int row = blockIdx.x;
    const int t   = threadIdx.x;
    const size_t base = (size_t)row * DMODEL + t * 4;

    float4 a = *(const float4*)&queries[base];
    float4 b = *(const float4*)&g_O[base];
    float x[4] = {a.x + b.x, a.y + b.y, a.z + b.z, a.w + b.w};

    float s = x[0] + x[1] + x[2] + x[3];
    s = block_sum256(s, red);
    float mean = s * (1.0f / DMODEL);

    float d[4] = {x[0] - mean, x[1] - mean, x[2] - mean, x[3] - mean};
    float ss = d[0] * d[0] + d[1] * d[1] + d[2] * d[2] + d[3] * d[3];
    ss = block_sum256(ss, red);
    float rstd = rsqrtf(ss * (1.0f / DMODEL) + LNEPS);

    float4 g  = *(const float4*)&gamma[t * 4];
    float4 be = *(const float4*)&beta[t * 4];
    float4 y = make_float4(g.x * d[0] * rstd + be.x,
                           g.y * d[1] * rstd + be.y,
                           g.z * d[2] * rstd + be.z,
                           g.w * d[3] * rstd + be.w);
    *(float4*)&out[base] = y;
}

// =================================================================
extern "C" void kernel_launch(void* const* d_in, const int* in_sizes, int n_in,
                              void* d_out, int out_size)
{
    const float* queries = (const float*)d_in[0];
    const float* keys    = (const float*)d_in[1];
    const float* values  = (const float*)d_in[2];
    const int*   qmask   = (const int*)d_in[3];
    const int*   kmask   = (const int*)d_in[4];
    const float* Wq      = (const float*)d_in[5];
    const float* Wk      = (const float*)d_in[6];
    const float* Wv      = (const float*)d_in[7];
    const float* gamma   = (const float*)d_in[8];
    const float* beta    = (const float*)d_in[9];
    float* out = (float*)d_out;

    cudaFuncSetAttribute(proj_mma_kernel,
                         cudaFuncAttributeMaxDynamicSharedMemorySize, PRJ_SMEM);
    cudaFuncSetAttribute(attn_mma_kernel,
                         cudaFuncAttributeMaxDynamicSharedMemorySize, AT_SMEM);

    convert_all_kernel<<<3 * XB + 3 * WB, 256>>>(queries, keys, values, Wq, Wk, Wv);

    proj_mma_kernel<<<dim3(DMODEL / 128, (BATCH * SEQ) / 128, 3), 256, PRJ_SMEM>>>();

    attn_mma_kernel<<<dim3(SEQ / 64, NHEAD, BATCH), 128, AT_SMEM>>>(qmask, kmask);

    ln_kernel<<<BATCH * SEQ, 256>>>(queries, gamma, beta, out);
}

// round 9
// speedup vs baseline: 1.1303x; 1.1228x over previous
#include <cuda_runtime.h>
#include <cuda_bf16.h>
#include <cstdint>

#define BATCH 4
#define SEQ   1024
#define DMODEL 1024
#define NHEAD 16
#define HDIM  64
#define PADV  (-1e7f)
#define LNEPS 1e-3f
#define NTOT  (BATCH*SEQ*DMODEL)   // 4194304
#define WTOT  (DMODEL*DMODEL)      // 1048576

// ---------------- scratch (device globals; no allocations) ----------------
__device__ __nv_bfloat16 g_Xh[3][NTOT];   // split inputs  (q,k,v)
__device__ __nv_bfloat16 g_Xl[3][NTOT];
__device__ __nv_bfloat16 g_Wh[3][WTOT];   // split weights
__device__ __nv_bfloat16 g_Wl[3][WTOT];
__device__ __nv_bfloat16 g_Ph[3][NTOT];   // projected Q,K,V (hi)
__device__ __nv_bfloat16 g_Pl[3][NTOT];   // projected Q,K,V (lo)
__device__ float g_O[NTOT];               // attention output (fp32)

// =================================================================
// helpers
// =================================================================
__device__ __forceinline__ uint32_t smem_u32(const void* p) {
    uint32_t a;
    asm("{ .reg .u64 t; cvta.to.shared.u64 t, %1; cvt.u32.u64 %0, t; }"
        : "=r"(a) : "l"(p));
    return a;
}

__device__ __forceinline__ void ldsm_x4(uint32_t* r, uint32_t addr) {
    asm volatile("ldmatrix.sync.aligned.m8n8.x4.shared.b16 {%0,%1,%2,%3}, [%4];"
                 : "=r"(r[0]), "=r"(r[1]), "=r"(r[2]), "=r"(r[3]) : "r"(addr));
}
__device__ __forceinline__ void ldsm_x4t(uint32_t* r, uint32_t addr) {
    asm volatile("ldmatrix.sync.aligned.m8n8.x4.trans.shared.b16 {%0,%1,%2,%3}, [%4];"
                 : "=r"(r[0]), "=r"(r[1]), "=r"(r[2]), "=r"(r[3]) : "r"(addr));
}
__device__ __forceinline__ void mma_bf16(float* d, const uint32_t* a, const uint32_t* b) {
    asm volatile(
        "mma.sync.aligned.m16n8k16.row.col.f32.bf16.bf16.f32 "
        "{%0,%1,%2,%3}, {%4,%5,%6,%7}, {%8,%9}, {%0,%1,%2,%3};"
        : "+f"(d[0]), "+f"(d[1]), "+f"(d[2]), "+f"(d[3])
        : "r"(a[0]), "r"(a[1]), "r"(a[2]), "r"(a[3]), "r"(b[0]), "r"(b[1]));
}

#define CP16(dst, src) \
    asm volatile("cp.async.cg.shared.global [%0], [%1], 16;" :: "r"(dst), "l"(src))
#define CP_COMMIT() asm volatile("cp.async.commit_group;" ::: "memory")
#define CP_WAIT(n)  asm volatile("cp.async.wait_group %0;" :: "n"(n) : "memory")

__device__ __forceinline__ uint32_t pack2(__nv_bfloat16 a, __nv_bfloat16 b) {
    return (uint32_t)__bfloat16_as_ushort(a) | ((uint32_t)__bfloat16_as_ushort(b) << 16);
}
__device__ __forceinline__ void split4(float4 v, uint2& hi, uint2& lo) {
    __nv_bfloat16 h0 = __float2bfloat16_rn(v.x);
    __nv_bfloat16 h1 = __float2bfloat16_rn(v.y);
    __nv_bfloat16 h2 = __float2bfloat16_rn(v.z);
    __nv_bfloat16 h3 = __float2bfloat16_rn(v.w);
    hi = make_uint2(pack2(h0, h1), pack2(h2, h3));
    lo = make_uint2(
        pack2(__float2bfloat16_rn(v.x - __bfloat162float(h0)),
              __float2bfloat16_rn(v.y - __bfloat162float(h1))),
        pack2(__float2bfloat16_rn(v.z - __bfloat162float(h2)),
              __float2bfloat16_rn(v.w - __bfloat162float(h3))));
}
// split a float pair into packed hi; return lo via out-param
__device__ __forceinline__ uint32_t splitpair(float x, float y, uint32_t& lo) {
    __nv_bfloat16 hx = __float2bfloat16_rn(x);
    __nv_bfloat16 hy = __float2bfloat16_rn(y);
    lo = pack2(__float2bfloat16_rn(x - __bfloat162float(hx)),
               __float2bfloat16_rn(y - __bfloat162float(hy)));
    return pack2(hx, hy);
}

// =================================================================
// Kernel 0: fused fp32 -> bf16 hi/lo preconversion for all 6 arrays.
// =================================================================
#define XB (NTOT / 1024)   // 4096
#define WB (WTOT / 1024)   // 1024

__global__ __launch_bounds__(256) void convert_all_kernel(
    const float* __restrict__ Xq, const float* __restrict__ Xk, const float* __restrict__ Xv,
    const float* __restrict__ Wq, const float* __restrict__ Wk, const float* __restrict__ Wv)
{
    int bid = blockIdx.x;
    const float* src;
    __nv_bfloat16 *hp, *lp;
    int off;
    if (bid < 3 * XB) {
        int job = bid / XB;
        off = (bid % XB) * 256 + threadIdx.x;
        src = (job == 0) ? Xq : (job == 1) ? Xk : Xv;
        hp = g_Xh[job];
        lp = g_Xl[job];
    } else {
        int r = bid - 3 * XB;
        int job = r / WB;
        off = (r % WB) * 256 + threadIdx.x;
        src = (job == 0) ? Wq : (job == 1) ? Wk : Wv;
        hp = g_Wh[job];
        lp = g_Wl[job];
    }
    float4 v = ((const float4*)src)[off];
    uint2 hi, lo;
    split4(v, hi, lo);
    ((uint2*)hp)[off] = hi;
    ((uint2*)lp)[off] = lo;
}

// =================================================================
// Kernel 1: QKV projections, mma.sync bf16 split-2, cp.async 2-stage,
// issue-BEFORE-wait (R6 discipline), reg-capped for 2 CTAs/SM.
// CTA tile 128x128, BK=32, 8 warps (2x4), warp tile 64x32.
// =================================================================
#define PA 40      // A pitch (bf16): 80 B rows
#define PB 136     // B pitch (bf16): 272 B rows
#define PRJ_AH 0
#define PRJ_AL 10240
#define PRJ_BH 20480
#define PRJ_BL 29184
#define PRJ_STAGE 37888
#define PRJ_SMEM (2 * PRJ_STAGE)   // 75776

__global__ __launch_bounds__(256, 2) void proj_mma_kernel()
{
    const int z = blockIdx.z;
    const __nv_bfloat16* Xh = g_Xh[z];
    const __nv_bfloat16* Xl = g_Xl[z];
    const __nv_bfloat16* Wh = g_Wh[z];
    const __nv_bfloat16* Wl = g_Wl[z];
    __nv_bfloat16* Ph = g_Ph[z];
    __nv_bfloat16* Pl = g_Pl[z];

    extern __shared__ char smem[];
    const uint32_t sb = smem_u32(smem);

    const int tid  = threadIdx.x;
    const int lane = tid & 31;
    const int wid  = tid >> 5;
    const int wm   = (wid >> 2) * 64;
    const int wn   = (wid & 3) * 32;
    const int rowBase = blockIdx.y * 128;
    const int colBase = blockIdx.x * 128;
    const int arow = lane & 15;
    const int acol = (lane >> 4) * 8;

    auto issue = [&](int it) {
        const uint32_t stb = sb + (uint32_t)(it & 1) * PRJ_STAGE;
        const int k0 = it * 32;
#pragma unroll
        for (int i = 0; i < 8; i++) {
            int idx = i * 256 + tid;
            if (idx < 1024) {                 // A tile: 128 rows x 32 k
                int half = idx >> 9;
                int j = idx & 511;
                int r = j >> 2, g = j & 3;
                const __nv_bfloat16* src =
                    (half ? Xl : Xh) + (size_t)(rowBase + r) * DMODEL + k0 + g * 8;
                CP16(stb + (half ? PRJ_AL : PRJ_AH) + r * 80 + g * 16, src);
            } else {                          // B tile: 32 k-rows x 128 n
                int j = idx - 1024;
                int half = j >> 9;
                j &= 511;
                int r = j >> 4, cc = j & 15;
                const __nv_bfloat16* src =
                    (half ? Wl : Wh) + (size_t)(k0 + r) * DMODEL + colBase + cc * 8;
                CP16(stb + (half ? PRJ_BL : PRJ_BH) + r * 272 + cc * 16, src);
            }
        }
        CP_COMMIT();
    };

    float acc[4][4][4];
#pragma unroll
    for (int i = 0; i < 4; i++)
#pragma unroll
        for (int j = 0; j < 4; j++)
#pragma unroll
            for (int u = 0; u < 4; u++) acc[i][j][u] = 0.0f;

    issue(0);

    for (int it = 0; it < 32; ++it) {
        if (it < 31) issue(it + 1);
        if (it < 31) { CP_WAIT(1); } else { CP_WAIT(0); }
        __syncthreads();

        const uint32_t stb = sb + (uint32_t)(it & 1) * PRJ_STAGE;
#pragma unroll
        for (int kb = 0; kb < 32; kb += 16) {
            uint32_t ah[4][4], al[4][4];
#pragma unroll
            for (int mb = 0; mb < 4; mb++) {
                uint32_t off = (uint32_t)((wm + mb * 16 + arow) * PA + kb + acol) * 2;
                ldsm_x4(ah[mb], stb + PRJ_AH + off);
                ldsm_x4(al[mb], stb + PRJ_AL + off);
            }
            uint32_t bh[2][4], bl[2][4];
#pragma unroll
            for (int nb2 = 0; nb2 < 2; nb2++) {
                uint32_t off = (uint32_t)((kb + arow) * PB + wn + nb2 * 16 + acol) * 2;
                ldsm_x4t(bh[nb2], stb + PRJ_BH + off);
                ldsm_x4t(bl[nb2], stb + PRJ_BL + off);
            }
#pragma unroll
            for (int mb = 0; mb < 4; mb++)
#pragma unroll
                for (int nb = 0; nb < 4; nb++) {
                    const uint32_t* ph = &bh[nb >> 1][(nb & 1) * 2];
                    const uint32_t* pl = &bl[nb >> 1][(nb & 1) * 2];
                    mma_bf16(acc[mb][nb], ah[mb], ph);
                    mma_bf16(acc[mb][nb], al[mb], ph);
                    mma_bf16(acc[mb][nb], ah[mb], pl);
                }
        }
        __syncthreads();
    }

    // epilogue: split fp32 acc into bf16 hi/lo and store
    const int grp = lane >> 2;
    const int qd  = lane & 3;
#pragma unroll
    for (int mb = 0; mb < 4; mb++) {
#pragma unroll
        for (int nb = 0; nb < 4; nb++) {
            size_t row = (size_t)(rowBase + wm + mb * 16 + grp);
            size_t col = (size_t)(colBase + wn + nb * 8 + qd * 2);
            uint32_t lo0, lo1;
            uint32_t hi0 = splitpair(acc[mb][nb][0], acc[mb][nb][1], lo0);
            uint32_t hi1 = splitpair(acc[mb][nb][2], acc[mb][nb][3], lo1);
            *(uint32_t*)&Ph[row * DMODEL + col] = hi0;
            *(uint32_t*)&Pl[row * DMODEL + col] = lo0;
            *(uint32_t*)&Ph[(row + 8) * DMODEL + col] = hi1;
            *(uint32_t*)&Pl[(row + 8) * DMODEL + col] = lo1;
        }
    }
}

// =================================================================
// Kernel 2: flash attention on mma.sync, bf16 split-2 throughout.
// CTA = (64 queries, head h, batch b); 4 warps x 16 query rows.
// K/V tiles (64 keys) cp.async double-buffered, issue-before-wait
// (exact R6 pipeline).
// =================================================================
#define ATP 72              // smem pitch (bf16) for 64-wide tiles: 144 B rows
#define AT_KH 0
#define AT_KL 9216
#define AT_VH 18432
#define AT_VL 27648
#define AT_STAGE 36864
#define AT_KM (2 * AT_STAGE)           // int[2][64] at byte 73728
#define AT_SMEM (AT_KM + 2 * 64 * 4)   // 74240

__global__ __launch_bounds__(128) void attn_mma_kernel(
    const int* __restrict__ qmask, const int* __restrict__ kmask)
{
    extern __shared__ char smem[];
    const uint32_t sb = smem_u32(smem);
    int* sKm = (int*)(smem + AT_KM);

    const int tid  = threadIdx.x;
    const int lane = tid & 31;
    const int wid  = tid >> 5;
    const int grp  = lane >> 2;
    const int qc   = lane & 3;
    const int arow = lane & 15;
    const int acol = (lane >> 4) * 8;

    const int q0 = blockIdx.x * 64;
    const int h  = blockIdx.y;
    const int b  = blockIdx.z;
    const size_t rowB = (size_t)b * SEQ;
    const size_t hoff = (size_t)h * HDIM;

    const __nv_bfloat16* Qh = g_Ph[0];
    const __nv_bfloat16* Ql = g_Pl[0];
    const __nv_bfloat16* Kh = g_Ph[1];
    const __nv_bfloat16* Kl = g_Pl[1];
    const __nv_bfloat16* Vh = g_Ph[2];
    const __nv_bfloat16* Vl = g_Pl[2];

    auto issue = [&](int it) {
        const int s = it & 1;
        const int k0 = it * 64;
        const uint32_t stb = sb + (uint32_t)s * AT_STAGE;
#pragma unroll
        for (int i = 0; i < 16; i++) {
            int idx = i * 128 + tid;          // 0..2047
            int arr = idx >> 9;
            int rem = idx & 511;
            int r = rem >> 3, cc = rem & 7;
            const __nv_bfloat16* base =
                (arr == 0) ? Kh : (arr == 1) ? Kl : (arr == 2) ? Vh : Vl;
            const __nv_bfloat16* src = base + (rowB + k0 + r) * DMODEL + hoff + cc * 8;
            CP16(stb + (uint32_t)arr * 9216 + r * 144 + cc * 16, src);
        }
        if (tid < 64) sKm[s * 64 + tid] = kmask[rowB + k0 + tid];
        CP_COMMIT();
    };

    issue(0);

    // ---- Q fragments straight from global (hi/lo), register-resident ----
    const int gq0 = q0 + wid * 16 + grp;      // global query row (and +8)
    uint32_t qfh[4][4], qfl[4][4];
    {
        const size_t r0 = (rowB + gq0) * DMODEL + hoff + 2 * qc;
#pragma unroll
        for (int kb = 0; kb < 4; kb++) {
            size_t base = r0 + kb * 16;
            qfh[kb][0] = *(const uint32_t*)&Qh[base];
            qfh[kb][1] = *(const uint32_t*)&Qh[base + 8 * DMODEL];
            qfh[kb][2] = *(const uint32_t*)&Qh[base + 8];
            qfh[kb][3] = *(const uint32_t*)&Qh[base + 8 * DMODEL + 8];
            qfl[kb][0] = *(const uint32_t*)&Ql[base];
            qfl[kb][1] = *(const uint32_t*)&Ql[base + 8 * DMODEL];
            qfl[kb][2] = *(const uint32_t*)&Ql[base + 8];
            qfl[kb][3] = *(const uint32_t*)&Ql[base + 8 * DMODEL + 8];
        }
    }

    float out[8][4];
#pragma unroll
    for (int nb = 0; nb < 8; nb++)
#pragma unroll
        for (int u = 0; u < 4; u++) out[nb][u] = 0.0f;
    float m0 = -1e30f, m1 = -1e30f, l0 = 0.0f, l1 = 0.0f;

    for (int it = 0; it < SEQ / 64; ++it) {
        if (it < 15) issue(it + 1);
        if (it < 15) { CP_WAIT(1); } else { CP_WAIT(0); }
        __syncthreads();

        const int s = it & 1;
        const uint32_t stb = sb + (uint32_t)s * AT_STAGE;
        const int* km = &sKm[s * 64];

        // ---- scores S = Q K^T ----
        float sc[8][4];
#pragma unroll
        for (int nb = 0; nb < 8; nb++)
#pragma unroll
            for (int u = 0; u < 4; u++) sc[nb][u] = 0.0f;

#pragma unroll
        for (int kb = 0; kb < 4; kb++) {
            uint32_t bkh[4][4], bkl[4][4];
#pragma unroll
            for (int nb2 = 0; nb2 < 4; nb2++) {
                uint32_t off = (uint32_t)((nb2 * 16 + arow) * ATP + kb * 16 + acol) * 2;
                ldsm_x4(bkh[nb2], stb + AT_KH + off);   // K stored [key][d]: non-trans
                ldsm_x4(bkl[nb2], stb + AT_KL + off);
            }
#pragma unroll
            for (int nb = 0; nb < 8; nb++) {
                int g2 = nb >> 1, sub = nb & 1;
                uint32_t bh[2] = {bkh[g2][sub], bkh[g2][sub + 2]};
                uint32_t bl[2] = {bkl[g2][sub], bkl[g2][sub + 2]};
                mma_bf16(sc[nb], qfh[kb], bh);
                mma_bf16(sc[nb], qfl[kb], bh);
                mma_bf16(sc[nb], qfh[kb], bl);
            }
        }

        // ---- scale + key mask ----
#pragma unroll
        for (int nb = 0; nb < 8; nb++) {
            int c0 = nb * 8 + 2 * qc;
            int k0m = km[c0], k1m = km[c0 + 1];
            sc[nb][0] = k0m ? sc[nb][0] * 0.125f : PADV;
            sc[nb][1] = k1m ? sc[nb][1] * 0.125f : PADV;
            sc[nb][2] = k0m ? sc[nb][2] * 0.125f : PADV;
            sc[nb][3] = k1m ? sc[nb][3] * 0.125f : PADV;
        }

        // ---- online softmax (rows gq0 and gq0+8) ----
        float mx0 = -1e30f, mx1 = -1e30f;
#pragma unroll
        for (int nb = 0; nb < 8; nb++) {
            mx0 = fmaxf(mx0, fmaxf(sc[nb][0], sc[nb][1]));
            mx1 = fmaxf(mx1, fmaxf(sc[nb][2], sc[nb][3]));
        }
        mx0 = fmaxf(mx0, __shfl_xor_sync(0xffffffffu, mx0, 1));
        mx0 = fmaxf(mx0, __shfl_xor_sync(0xffffffffu, mx0, 2));
        mx1 = fmaxf(mx1, __shfl_xor_sync(0xffffffffu, mx1, 1));
        mx1 = fmaxf(mx1, __shfl_xor_sync(0xffffffffu, mx1, 2));
        float mn0 = fmaxf(m0, mx0), mn1 = fmaxf(m1, mx1);
        float a0 = __expf(m0 - mn0), a1 = __expf(m1 - mn1);
        float rs0 = 0.0f, rs1 = 0.0f;
#pragma unroll
        for (int nb = 0; nb < 8; nb++) {
            sc[nb][0] = __expf(sc[nb][0] - mn0); rs0 += sc[nb][0];
            sc[nb][1] = __expf(sc[nb][1] - mn0); rs0 += sc[nb][1];
            sc[nb][2] = __expf(sc[nb][2] - mn1); rs1 += sc[nb][2];
            sc[nb][3] = __expf(sc[nb][3] - mn1); rs1 += sc[nb][3];
        }
        rs0 += __shfl_xor_sync(0xffffffffu, rs0, 1);
        rs0 += __shfl_xor_sync(0xffffffffu, rs0, 2);
        rs1 += __shfl_xor_sync(0xffffffffu, rs1, 1);
        rs1 += __shfl_xor_sync(0xffffffffu, rs1, 2);
        l0 = l0 * a0 + rs0;
        l1 = l1 * a1 + rs1;
        m0 = mn0;
        m1 = mn1;
#pragma unroll
        for (int nb = 0; nb < 8; nb++) {
            out[nb][0] *= a0; out[nb][1] *= a0;
            out[nb][2] *= a1; out[nb][3] *= a1;
        }

        // ---- O += P V : repack P C-frags -> bf16 A-frags in-register ----
#pragma unroll
        for (int kb = 0; kb < 4; kb++) {
            uint32_t pah[4], pal[4];
            pah[0] = splitpair(sc[2 * kb][0],     sc[2 * kb][1],     pal[0]);
            pah[1] = splitpair(sc[2 * kb][2],     sc[2 * kb][3],     pal[1]);
            pah[2] = splitpair(sc[2 * kb + 1][0], sc[2 * kb + 1][1], pal[2]);
            pah[3] = splitpair(sc[2 * kb + 1][2], sc[2 * kb + 1][3], pal[3]);

            uint32_t bvh[4][4], bvl[4][4];
#pragma unroll
            for (int nb2 = 0; nb2 < 4; nb2++) {
                uint32_t off = (uint32_t)((kb * 16 + arow) * ATP + nb2 * 16 + acol) * 2;
                ldsm_x4t(bvh[nb2], stb + AT_VH + off);   // V stored [key][d]: trans
                ldsm_x4t(bvl[nb2], stb + AT_VL + off);
            }
#pragma unroll
            for (int nb = 0; nb < 8; nb++) {
                int g2 = nb >> 1, sub = nb & 1;
                const uint32_t* bh = &bvh[g2][2 * sub];
                const uint32_t* bl = &bvl[g2][2 * sub];
                mma_bf16(out[nb], pah, bh);
                mma_bf16(out[nb], pal, bh);
                mma_bf16(out[nb], pah, bl);
            }
        }
        __syncthreads();
    }

    // ---- finalize: 1/l, query mask, fp32 store ----
    float s0 = (float)qmask[rowB + gq0]     / l0;
    float s1 = (float)qmask[rowB + gq0 + 8] / l1;
#pragma unroll
    for (int nb = 0; nb < 8; nb++) {
        size_t col = hoff + nb * 8 + 2 * qc;
        *(float2*)&g_O[(rowB + gq0) * DMODEL + col] =
            make_float2(out[nb][0] * s0, out[nb][1] * s0);
        *(float2*)&g_O[(rowB + gq0 + 8) * DMODEL + col] =
            make_float2(out[nb][2] * s1, out[nb][3] * s1);
    }
}

// =================================================================
// Kernel 3: residual + LayerNorm per row (unchanged)
// =================================================================
__device__ __forceinline__ float block_sum256(float v, float* red)
{
#pragma unroll
    for (int off = 16; off; off >>= 1)
        v += __shfl_xor_sync(0xffffffffu, v, off);
    if ((threadIdx.x & 31) == 0) red[threadIdx.x >> 5] = v;
    __syncthreads();
    float tot = 0.0f;
#pragma unroll
    for (int w = 0; w < 8; w++) tot += red[w];
    __syncthreads();
    return tot;
}

__global__ __launch_bounds__(256) void ln_kernel(
    const float* __restrict__ queries,
    const float* __restrict__ gamma,
    const float* __restrict__ beta,
    float* __restrict__ out)
{
    __shared__ float red[8];
    const int row = blockIdx.x;
    const int t   = threadIdx.x;
    const size_t base = (size_t)row * DMODEL + t * 4;

    float4 a = *(const float4*)&queries[base];
    float4 b = *(const float4*)&g_O[base];
    float x[4] = {a.x + b.x, a.y + b.y, a.z + b.z, a.w + b.w};

    float s = x[0] + x[1] + x[2] + x[3];
    s = block_sum256(s, red);
    float mean = s * (1.0f / DMODEL);

    float d[4] = {x[0] - mean, x[1] - mean, x[2] - mean, x[3] - mean};
    float ss = d[0] * d[0] + d[1] * d[1] + d[2] * d[2] + d[3] * d[3];
    ss = block_sum256(ss, red);
    float rstd = rsqrtf(ss * (1.0f / DMODEL) + LNEPS);

    float4 g  = *(const float4*)&gamma[t * 4];
    float4 be = *(const float4*)&beta[t * 4];
    float4 y = make_float4(g.x * d[0] * rstd + be.x,
                           g.y * d[1] * rstd + be.y,
                           g.z * d[2] * rstd + be.z,
                           g.w * d[3] * rstd + be.w);
    *(float4*)&out[base] = y;
}

// =================================================================
extern "C" void kernel_launch(void* const* d_in, const int* in_sizes, int n_in,
                              void* d_out, int out_size)
{
    const float* queries = (const float*)d_in[0];
    const float* keys    = (const float*)d_in[1];
    const float* values  = (const float*)d_in[2];
    const int*   qmask   = (const int*)d_in[3];
    const int*   kmask   = (const int*)d_in[4];
    const float* Wq      = (const float*)d_in[5];
    const float* Wk      = (const float*)d_in[6];
    const float* Wv      = (const float*)d_in[7];
    const float* gamma   = (const float*)d_in[8];
    const float* beta    = (const float*)d_in[9];
    float* out = (float*)d_out;

    cudaFuncSetAttribute(proj_mma_kernel,
                         cudaFuncAttributeMaxDynamicSharedMemorySize, PRJ_SMEM);
    cudaFuncSetAttribute(attn_mma_kernel,
                         cudaFuncAttributeMaxDynamicSharedMemorySize, AT_SMEM);

    convert_all_kernel<<<3 * XB + 3 * WB, 256>>>(queries, keys, values, Wq, Wk, Wv);

    proj_mma_kernel<<<dim3(DMODEL / 128, (BATCH * SEQ) / 128, 3), 256, PRJ_SMEM>>>();

    attn_mma_kernel<<<dim3(SEQ / 64, NHEAD, BATCH), 128, AT_SMEM>>>(qmask, kmask);

    ln_kernel<<<BATCH * SEQ, 256>>>(queries, gamma, beta, out);
}

// round 10
// speedup vs baseline: 1.5056x; 1.3321x over previous
#include <cuda_runtime.h>
#include <cuda_fp16.h>
#include <cstdint>

#define BATCH 4
#define SEQ   1024
#define DMODEL 1024
#define NHEAD 16
#define HDIM  64
#define PADV  (-1e7f)
#define LNEPS 1e-3f
#define NTOT  (BATCH*SEQ*DMODEL)   // 4194304
#define WTOT  (DMODEL*DMODEL)      // 1048576

// ---------------- scratch (device globals; no allocations) ----------------
__device__ __half g_Xh[3][NTOT];   // split inputs (q,k,v): hi
__device__ __half g_Xl[3][NTOT];   // split inputs: lo
__device__ __half g_Wh[3][WTOT];   // weights: hi only (B-side single)
__device__ __half g_Ph[3][NTOT];   // projected Q,K,V: hi
__device__ __half g_Pl[3][NTOT];   // projected Q: lo (written for z==0 only)
__device__ float  g_O[NTOT];       // attention output (fp32)

// =================================================================
// helpers
// =================================================================
__device__ __forceinline__ uint32_t smem_u32(const void* p) {
    uint32_t a;
    asm("{ .reg .u64 t; cvta.to.shared.u64 t, %1; cvt.u32.u64 %0, t; }"
        : "=r"(a) : "l"(p));
    return a;
}

__device__ __forceinline__ void ldsm_x4(uint32_t* r, uint32_t addr) {
    asm volatile("ldmatrix.sync.aligned.m8n8.x4.shared.b16 {%0,%1,%2,%3}, [%4];"
                 : "=r"(r[0]), "=r"(r[1]), "=r"(r[2]), "=r"(r[3]) : "r"(addr));
}
__device__ __forceinline__ void ldsm_x4t(uint32_t* r, uint32_t addr) {
    asm volatile("ldmatrix.sync.aligned.m8n8.x4.trans.shared.b16 {%0,%1,%2,%3}, [%4];"
                 : "=r"(r[0]), "=r"(r[1]), "=r"(r[2]), "=r"(r[3]) : "r"(addr));
}
__device__ __forceinline__ void mma_fp16(float* d, const uint32_t* a, const uint32_t* b) {
    asm volatile(
        "mma.sync.aligned.m16n8k16.row.col.f32.f16.f16.f32 "
        "{%0,%1,%2,%3}, {%4,%5,%6,%7}, {%8,%9}, {%0,%1,%2,%3};"
        : "+f"(d[0]), "+f"(d[1]), "+f"(d[2]), "+f"(d[3])
        : "r"(a[0]), "r"(a[1]), "r"(a[2]), "r"(a[3]), "r"(b[0]), "r"(b[1]));
}

#define CP16(dst, src) \
    asm volatile("cp.async.cg.shared.global [%0], [%1], 16;" :: "r"(dst), "l"(src))
#define CP_COMMIT() asm volatile("cp.async.commit_group;" ::: "memory")
#define CP_WAIT(n)  asm volatile("cp.async.wait_group %0;" :: "n"(n) : "memory")

__device__ __forceinline__ uint32_t pack2h(__half a, __half b) {
    return (uint32_t)__half_as_ushort(a) | ((uint32_t)__half_as_ushort(b) << 16);
}
__device__ __forceinline__ void split4h(float4 v, uint2& hi, uint2& lo) {
    __half h0 = __float2half_rn(v.x);
    __half h1 = __float2half_rn(v.y);
    __half h2 = __float2half_rn(v.z);
    __half h3 = __float2half_rn(v.w);
    hi = make_uint2(pack2h(h0, h1), pack2h(h2, h3));
    lo = make_uint2(
        pack2h(__float2half_rn(v.x - __half2float(h0)),
               __float2half_rn(v.y - __half2float(h1))),
        pack2h(__float2half_rn(v.z - __half2float(h2)),
               __float2half_rn(v.w - __half2float(h3))));
}
__device__ __forceinline__ uint2 cvt4h(float4 v) {
    return make_uint2(pack2h(__float2half_rn(v.x), __float2half_rn(v.y)),
                      pack2h(__float2half_rn(v.z), __float2half_rn(v.w)));
}
// split a float pair into packed fp16 hi; return lo via out-param
__device__ __forceinline__ uint32_t splitpair_h(float x, float y, uint32_t& lo) {
    __half hx = __float2half_rn(x);
    __half hy = __float2half_rn(y);
    lo = pack2h(__float2half_rn(x - __half2float(hx)),
                __float2half_rn(y - __half2float(hy)));
    return pack2h(hx, hy);
}

// =================================================================
// Kernel 0: fused fp32 -> fp16 preconversion.
// X jobs (hi+lo); W jobs (hi only).
// =================================================================
#define XB (NTOT / 1024)   // 4096
#define WB (WTOT / 1024)   // 1024

__global__ __launch_bounds__(256) void convert_all_kernel(
    const float* __restrict__ Xq, const float* __restrict__ Xk, const float* __restrict__ Xv,
    const float* __restrict__ Wq, const float* __restrict__ Wk, const float* __restrict__ Wv)
{
    int bid = blockIdx.x;
    if (bid < 3 * XB) {
        int job = bid / XB;
        int off = (bid % XB) * 256 + threadIdx.x;
        const float* src = (job == 0) ? Xq : (job == 1) ? Xk : Xv;
        float4 v = ((const float4*)src)[off];
        uint2 hi, lo;
        split4h(v, hi, lo);
        ((uint2*)g_Xh[job])[off] = hi;
        ((uint2*)g_Xl[job])[off] = lo;
    } else {
        int r = bid - 3 * XB;
        int job = r / WB;
        int off = (r % WB) * 256 + threadIdx.x;
        const float* src = (job == 0) ? Wq : (job == 1) ? Wk : Wv;
        float4 v = ((const float4*)src)[off];
        ((uint2*)g_Wh[job])[off] = cvt4h(v);
    }
}

// =================================================================
// Kernel 1: QKV projections, mma.sync fp16 split-2 (A=hi+lo, B=hi),
// cp.async 2-stage, issue-before-wait (R6 discipline).
// CTA tile 128x128, BK=32, 8 warps (2x4), warp tile 64x32.
// =================================================================
#define PA 40      // A pitch (fp16): 80 B rows
#define PB 136     // B pitch (fp16): 272 B rows
#define PRJ_AH 0
#define PRJ_AL 10240
#define PRJ_BH 20480
#define PRJ_STAGE 29184
#define PRJ_SMEM (2 * PRJ_STAGE)   // 58368

__global__ __launch_bounds__(256, 2) void proj_mma_kernel()
{
    const int z = blockIdx.z;
    const __half* Xh = g_Xh[z];
    const __half* Xl = g_Xl[z];
    const __half* Wh = g_Wh[z];
    __half* Ph = g_Ph[z];
    __half* Pl = g_Pl[z];

    extern __shared__ char smem[];
    const uint32_t sb = smem_u32(smem);

    const int tid  = threadIdx.x;
    const int lane = tid & 31;
    const int wid  = tid >> 5;
    const int wm   = (wid >> 2) * 64;
    const int wn   = (wid & 3) * 32;
    const int rowBase = blockIdx.y * 128;
    const int colBase = blockIdx.x * 128;
    const int arow = lane & 15;
    const int acol = (lane >> 4) * 8;

    auto issue = [&](int it) {
        const uint32_t stb = sb + (uint32_t)(it & 1) * PRJ_STAGE;
        const int k0 = it * 32;
#pragma unroll
        for (int i = 0; i < 6; i++) {
            int idx = i * 256 + tid;           // 0..1535
            if (idx < 1024) {                  // A hi/lo: 128 rows x 32 k
                int hf = idx >> 9;
                int j = idx & 511;
                int r = j >> 2, g = j & 3;
                const __half* src =
                    (hf ? Xl : Xh) + (size_t)(rowBase + r) * DMODEL + k0 + g * 8;
                CP16(stb + (hf ? PRJ_AL : PRJ_AH) + r * 80 + g * 16, src);
            } else {                           // B hi: 32 k-rows x 128 n
                int j = idx - 1024;
                int r = j >> 4, cc = j & 15;
                const __half* src =
                    Wh + (size_t)(k0 + r) * DMODEL + colBase + cc * 8;
                CP16(stb + PRJ_BH + r * 272 + cc * 16, src);
            }
        }
        CP_COMMIT();
    };

    float acc[4][4][4];
#pragma unroll
    for (int i = 0; i < 4; i++)
#pragma unroll
        for (int j = 0; j < 4; j++)
#pragma unroll
            for (int u = 0; u < 4; u++) acc[i][j][u] = 0.0f;

    issue(0);

    for (int it = 0; it < 32; ++it) {
        if (it < 31) issue(it + 1);
        if (it < 31) { CP_WAIT(1); } else { CP_WAIT(0); }
        __syncthreads();

        const uint32_t stb = sb + (uint32_t)(it & 1) * PRJ_STAGE;
#pragma unroll
        for (int kb = 0; kb < 32; kb += 16) {
            uint32_t ah[4][4], al[4][4];
#pragma unroll
            for (int mb = 0; mb < 4; mb++) {
                uint32_t off = (uint32_t)((wm + mb * 16 + arow) * PA + kb + acol) * 2;
                ldsm_x4(ah[mb], stb + PRJ_AH + off);
                ldsm_x4(al[mb], stb + PRJ_AL + off);
            }
            uint32_t bh[2][4];
#pragma unroll
            for (int nb2 = 0; nb2 < 2; nb2++) {
                uint32_t off = (uint32_t)((kb + arow) * PB + wn + nb2 * 16 + acol) * 2;
                ldsm_x4t(bh[nb2], stb + PRJ_BH + off);
            }
#pragma unroll
            for (int mb = 0; mb < 4; mb++)
#pragma unroll
                for (int nb = 0; nb < 4; nb++) {
                    const uint32_t* ph = &bh[nb >> 1][(nb & 1) * 2];
                    mma_fp16(acc[mb][nb], ah[mb], ph);
                    mma_fp16(acc[mb][nb], al[mb], ph);
                }
        }
        __syncthreads();
    }

    // epilogue: fp16 split store; lo needed only for Q (z==0)
    const int grp = lane >> 2;
    const int qd  = lane & 3;
#pragma unroll
    for (int mb = 0; mb < 4; mb++) {
#pragma unroll
        for (int nb = 0; nb < 4; nb++) {
            size_t row = (size_t)(rowBase + wm + mb * 16 + grp);
            size_t col = (size_t)(colBase + wn + nb * 8 + qd * 2);
            uint32_t lo0, lo1;
            uint32_t hi0 = splitpair_h(acc[mb][nb][0], acc[mb][nb][1], lo0);
            uint32_t hi1 = splitpair_h(acc[mb][nb][2], acc[mb][nb][3], lo1);
            *(uint32_t*)&Ph[row * DMODEL + col] = hi0;
            *(uint32_t*)&Ph[(row + 8) * DMODEL + col] = hi1;
            if (z == 0) {
                *(uint32_t*)&Pl[row * DMODEL + col] = lo0;
                *(uint32_t*)&Pl[(row + 8) * DMODEL + col] = lo1;
            }
        }
    }
}

// =================================================================
// Kernel 2: flash attention, mma.sync fp16 split-2.
// Q = hi+lo (register frags); K,V single fp16 in smem.
// CTA = (64 queries, head h, batch b); 4 warps x 16 query rows.
// K/V tiles cp.async double-buffered (R6 pipeline).
// =================================================================
#define ATP 72              // smem pitch (fp16): 144 B rows
#define AT_KH 0
#define AT_VH 9216
#define AT_STAGE 18432
#define AT_KM (2 * AT_STAGE)           // int[2][64] at byte 36864
#define AT_SMEM (AT_KM + 2 * 64 * 4)   // 37376

__global__ __launch_bounds__(128) void attn_mma_kernel(
    const int* __restrict__ qmask, const int* __restrict__ kmask)
{
    extern __shared__ char smem[];
    const uint32_t sb = smem_u32(smem);
    int* sKm = (int*)(smem + AT_KM);

    const int tid  = threadIdx.x;
    const int lane = tid & 31;
    const int wid  = tid >> 5;
    const int grp  = lane >> 2;
    const int qc   = lane & 3;
    const int arow = lane & 15;
    const int acol = (lane >> 4) * 8;

    const int q0 = blockIdx.x * 64;
    const int h  = blockIdx.y;
    const int b  = blockIdx.z;
    const size_t rowB = (size_t)b * SEQ;
    const size_t hoff = (size_t)h * HDIM;

    const __half* Qh = g_Ph[0];
    const __half* Ql = g_Pl[0];
    const __half* Kh = g_Ph[1];
    const __half* Vh = g_Ph[2];

    auto issue = [&](int it) {
        const int s = it & 1;
        const int k0 = it * 64;
        const uint32_t stb = sb + (uint32_t)s * AT_STAGE;
#pragma unroll
        for (int i = 0; i < 8; i++) {
            int idx = i * 128 + tid;          // 0..1023
            int arr = idx >> 9;               // 0 = K, 1 = V
            int rem = idx & 511;
            int r = rem >> 3, cc = rem & 7;
            const __half* base = arr ? Vh : Kh;
            const __half* src = base + (rowB + k0 + r) * DMODEL + hoff + cc * 8;
            CP16(stb + (uint32_t)arr * 9216 + r * 144 + cc * 16, src);
        }
        if (tid < 64) sKm[s * 64 + tid] = kmask[rowB + k0 + tid];
        CP_COMMIT();
    };

    issue(0);

    // ---- Q fragments straight from global (hi/lo), register-resident ----
    const int gq0 = q0 + wid * 16 + grp;      // global query row (and +8)
    uint32_t qfh[4][4], qfl[4][4];
    {
        const size_t r0 = (rowB + gq0) * DMODEL + hoff + 2 * qc;
#pragma unroll
        for (int kb = 0; kb < 4; kb++) {
            size_t base = r0 + kb * 16;
            qfh[kb][0] = *(const uint32_t*)&Qh[base];
            qfh[kb][1] = *(const uint32_t*)&Qh[base + 8 * DMODEL];
            qfh[kb][2] = *(const uint32_t*)&Qh[base + 8];
            qfh[kb][3] = *(const uint32_t*)&Qh[base + 8 * DMODEL + 8];
            qfl[kb][0] = *(const uint32_t*)&Ql[base];
            qfl[kb][1] = *(const uint32_t*)&Ql[base + 8 * DMODEL];
            qfl[kb][2] = *(const uint32_t*)&Ql[base + 8];
            qfl[kb][3] = *(const uint32_t*)&Ql[base + 8 * DMODEL + 8];
        }
    }

    float out[8][4];
#pragma unroll
    for (int nb = 0; nb < 8; nb++)
#pragma unroll
        for (int u = 0; u < 4; u++) out[nb][u] = 0.0f;
    float m0 = -1e30f, m1 = -1e30f, l0 = 0.0f, l1 = 0.0f;

    for (int it = 0; it < SEQ / 64; ++it) {
        if (it < 15) issue(it + 1);
        if (it < 15) { CP_WAIT(1); } else { CP_WAIT(0); }
        __syncthreads();

        const int s = it & 1;
        const uint32_t stb = sb + (uint32_t)s * AT_STAGE;
        const int* km = &sKm[s * 64];

        // ---- scores S = (Q_hi + Q_lo) K_hi^T ----
        float sc[8][4];
#pragma unroll
        for (int nb = 0; nb < 8; nb++)
#pragma unroll
            for (int u = 0; u < 4; u++) sc[nb][u] = 0.0f;

#pragma unroll
        for (int kb = 0; kb < 4; kb++) {
            uint32_t bkh[4][4];
#pragma unroll
            for (int nb2 = 0; nb2 < 4; nb2++) {
                uint32_t off = (uint32_t)((nb2 * 16 + arow) * ATP + kb * 16 + acol) * 2;
                ldsm_x4(bkh[nb2], stb + AT_KH + off);
            }
#pragma unroll
            for (int nb = 0; nb < 8; nb++) {
                int g2 = nb >> 1, sub = nb & 1;
                uint32_t bh[2] = {bkh[g2][sub], bkh[g2][sub + 2]};
                mma_fp16(sc[nb], qfh[kb], bh);
                mma_fp16(sc[nb], qfl[kb], bh);
            }
        }

        // ---- scale + key mask ----
#pragma unroll
        for (int nb = 0; nb < 8; nb++) {
            int c0 = nb * 8 + 2 * qc;
            int k0m = km[c0], k1m = km[c0 + 1];
            sc[nb][0] = k0m ? sc[nb][0] * 0.125f : PADV;
            sc[nb][1] = k1m ? sc[nb][1] * 0.125f : PADV;
            sc[nb][2] = k0m ? sc[nb][2] * 0.125f : PADV;
            sc[nb][3] = k1m ? sc[nb][3] * 0.125f : PADV;
        }

        // ---- online softmax (rows gq0 and gq0+8) ----
        float mx0 = -1e30f, mx1 = -1e30f;
#pragma unroll
        for (int nb = 0; nb < 8; nb++) {
            mx0 = fmaxf(mx0, fmaxf(sc[nb][0], sc[nb][1]));
            mx1 = fmaxf(mx1, fmaxf(sc[nb][2], sc[nb][3]));
        }
        mx0 = fmaxf(mx0, __shfl_xor_sync(0xffffffffu, mx0, 1));
        mx0 = fmaxf(mx0, __shfl_xor_sync(0xffffffffu, mx0, 2));
        mx1 = fmaxf(mx1, __shfl_xor_sync(0xffffffffu, mx1, 1));
        mx1 = fmaxf(mx1, __shfl_xor_sync(0xffffffffu, mx1, 2));
        float mn0 = fmaxf(m0, mx0), mn1 = fmaxf(m1, mx1);
        float a0 = __expf(m0 - mn0), a1 = __expf(m1 - mn1);
        float rs0 = 0.0f, rs1 = 0.0f;
#pragma unroll
        for (int nb = 0; nb < 8; nb++) {
            sc[nb][0] = __expf(sc[nb][0] - mn0); rs0 += sc[nb][0];
            sc[nb][1] = __expf(sc[nb][1] - mn0); rs0 += sc[nb][1];
            sc[nb][2] = __expf(sc[nb][2] - mn1); rs1 += sc[nb][2];
            sc[nb][3] = __expf(sc[nb][3] - mn1); rs1 += sc[nb][3];
        }
        rs0 += __shfl_xor_sync(0xffffffffu, rs0, 1);
        rs0 += __shfl_xor_sync(0xffffffffu, rs0, 2);
        rs1 += __shfl_xor_sync(0xffffffffu, rs1, 1);
        rs1 += __shfl_xor_sync(0xffffffffu, rs1, 2);
        l0 = l0 * a0 + rs0;
        l1 = l1 * a1 + rs1;
        m0 = mn0;
        m1 = mn1;
#pragma unroll
        for (int nb = 0; nb < 8; nb++) {
            out[nb][0] *= a0; out[nb][1] *= a0;
            out[nb][2] *= a1; out[nb][3] *= a1;
        }

        // ---- O += (P_hi + P_lo) V_hi ----
#pragma unroll
        for (int kb = 0; kb < 4; kb++) {
            uint32_t pah[4], pal[4];
            pah[0] = splitpair_h(sc[2 * kb][0],     sc[2 * kb][1],     pal[0]);
            pah[1] = splitpair_h(sc[2 * kb][2],     sc[2 * kb][3],     pal[1]);
            pah[2] = splitpair_h(sc[2 * kb + 1][0], sc[2 * kb + 1][1], pal[2]);
            pah[3] = splitpair_h(sc[2 * kb + 1][2], sc[2 * kb + 1][3], pal[3]);

            uint32_t bvh[4][4];
#pragma unroll
            for (int nb2 = 0; nb2 < 4; nb2++) {
                uint32_t off = (uint32_t)((kb * 16 + arow) * ATP + nb2 * 16 + acol) * 2;
                ldsm_x4t(bvh[nb2], stb + AT_VH + off);
            }
#pragma unroll
            for (int nb = 0; nb < 8; nb++) {
                int g2 = nb >> 1, sub = nb & 1;
                const uint32_t* bh = &bvh[g2][2 * sub];
                mma_fp16(out[nb], pah, bh);
                mma_fp16(out[nb], pal, bh);
            }
        }
        __syncthreads();
    }

    // ---- finalize: 1/l, query mask, fp32 store ----
    float s0 = (float)qmask[rowB + gq0]     / l0;
    float s1 = (float)qmask[rowB + gq0 + 8] / l1;
#pragma unroll
    for (int nb = 0; nb < 8; nb++) {
        size_t col = hoff + nb * 8 + 2 * qc;
        *(float2*)&g_O[(rowB + gq0) * DMODEL + col] =
            make_float2(out[nb][0] * s0, out[nb][1] * s0);
        *(float2*)&g_O[(rowB + gq0 + 8) * DMODEL + col] =
            make_float2(out[nb][2] * s1, out[nb][3] * s1);
    }
}

// =================================================================
// Kernel 3: residual + LayerNorm per row (unchanged)
// =================================================================
__device__ __forceinline__ float block_sum256(float v, float* red)
{
#pragma unroll
    for (int off = 16; off; off >>= 1)
        v += __shfl_xor_sync(0xffffffffu, v, off);
    if ((threadIdx.x & 31) == 0) red[threadIdx.x >> 5] = v;
    __syncthreads();
    float tot = 0.0f;
#pragma unroll
    for (int w = 0; w < 8; w++) tot += red[w];
    __syncthreads();
    return tot;
}

__global__ __launch_bounds__(256) void ln_kernel(
    const float* __restrict__ queries,
    const float* __restrict__ gamma,
    const float* __restrict__ beta,
    float* __restrict__ out)
{
    __shared__ float red[8];
    const int row = blockIdx.x;
    const int t   = threadIdx.x;
    const size_t base = (size_t)row * DMODEL + t * 4;

    float4 a = *(const float4*)&queries[base];
    float4 b = *(const float4*)&g_O[base];
    float x[4] = {a.x + b.x, a.y + b.y, a.z + b.z, a.w + b.w};

    float s = x[0] + x[1] + x[2] + x[3];
    s = block_sum256(s, red);
    float mean = s * (1.0f / DMODEL);

    float d[4] = {x[0] - mean, x[1] - mean, x[2] - mean, x[3] - mean};
    float ss = d[0] * d[0] + d[1] * d[1] + d[2] * d[2] + d[3] * d[3];
    ss = block_sum256(ss, red);
    float rstd = rsqrtf(ss * (1.0f / DMODEL) + LNEPS);

    float4 g  = *(const float4*)&gamma[t * 4];
    float4 be = *(const float4*)&beta[t * 4];
    float4 y = make_float4(g.x * d[0] * rstd + be.x,
                           g.y * d[1] * rstd + be.y,
                           g.z * d[2] * rstd + be.z,
                           g.w * d[3] * rstd + be.w);
    *(float4*)&out[base] = y;
}

// =================================================================
extern "C" void kernel_launch(void* const* d_in, const int* in_sizes, int n_in,
                              void* d_out, int out_size)
{
    const float* queries = (const float*)d_in[0];
    const float* keys    = (const float*)d_in[1];
    const float* values  = (const float*)d_in[2];
    const int*   qmask   = (const int*)d_in[3];
    const int*   kmask   = (const int*)d_in[4];
    const float* Wq      = (const float*)d_in[5];
    const float* Wk      = (const float*)d_in[6];
    const float* Wv      = (const float*)d_in[7];
    const float* gamma   = (const float*)d_in[8];
    const float* beta    = (const float*)d_in[9];
    float* out = (float*)d_out;

    cudaFuncSetAttribute(proj_mma_kernel,
                         cudaFuncAttributeMaxDynamicSharedMemorySize, PRJ_SMEM);
    cudaFuncSetAttribute(attn_mma_kernel,
                         cudaFuncAttributeMaxDynamicSharedMemorySize, AT_SMEM);

    convert_all_kernel<<<3 * XB + 3 * WB, 256>>>(queries, keys, values, Wq, Wk, Wv);

    proj_mma_kernel<<<dim3(DMODEL / 128, (BATCH * SEQ) / 128, 3), 256, PRJ_SMEM>>>();

    attn_mma_kernel<<<dim3(SEQ / 64, NHEAD, BATCH), 128, AT_SMEM>>>(qmask, kmask);

    ln_kernel<<<BATCH * SEQ, 256>>>(queries, gamma, beta, out);
}

// round 11
// speedup vs baseline: 2.4840x; 1.6498x over previous
#include <cuda_runtime.h>
#include <cuda_fp16.h>
#include <cstdint>

#define BATCH 4
#define SEQ   1024
#define DMODEL 1024
#define NHEAD 16
#define HDIM  64
#define PADV  (-1e7f)
#define LNEPS 1e-3f
#define NTOT  (BATCH*SEQ*DMODEL)   // 4194304
#define WTOT  (DMODEL*DMODEL)      // 1048576

// ---------------- scratch (device globals; no allocations) ----------------
__device__ __half g_X[3][NTOT];    // fp16 inputs (q,k,v)
__device__ __half g_W[3][WTOT];    // fp16 weights
__device__ __half g_P[3][NTOT];    // projected Q,K,V (fp16)
__device__ float  g_O[NTOT];       // attention output (fp32)

// =================================================================
// helpers
// =================================================================
__device__ __forceinline__ uint32_t smem_u32(const void* p) {
    uint32_t a;
    asm("{ .reg .u64 t; cvta.to.shared.u64 t, %1; cvt.u32.u64 %0, t; }"
        : "=r"(a) : "l"(p));
    return a;
}

__device__ __forceinline__ void ldsm_x4(uint32_t* r, uint32_t addr) {
    asm volatile("ldmatrix.sync.aligned.m8n8.x4.shared.b16 {%0,%1,%2,%3}, [%4];"
                 : "=r"(r[0]), "=r"(r[1]), "=r"(r[2]), "=r"(r[3]) : "r"(addr));
}
__device__ __forceinline__ void ldsm_x4t(uint32_t* r, uint32_t addr) {
    asm volatile("ldmatrix.sync.aligned.m8n8.x4.trans.shared.b16 {%0,%1,%2,%3}, [%4];"
                 : "=r"(r[0]), "=r"(r[1]), "=r"(r[2]), "=r"(r[3]) : "r"(addr));
}
__device__ __forceinline__ void mma_fp16(float* d, const uint32_t* a, const uint32_t* b) {
    asm volatile(
        "mma.sync.aligned.m16n8k16.row.col.f32.f16.f16.f32 "
        "{%0,%1,%2,%3}, {%4,%5,%6,%7}, {%8,%9}, {%0,%1,%2,%3};"
        : "+f"(d[0]), "+f"(d[1]), "+f"(d[2]), "+f"(d[3])
        : "r"(a[0]), "r"(a[1]), "r"(a[2]), "r"(a[3]), "r"(b[0]), "r"(b[1]));
}

#define CP16(dst, src) \
    asm volatile("cp.async.cg.shared.global [%0], [%1], 16;" :: "r"(dst), "l"(src))
#define CP_COMMIT() asm volatile("cp.async.commit_group;" ::: "memory")
#define CP_WAIT(n)  asm volatile("cp.async.wait_group %0;" :: "n"(n) : "memory")

__device__ __forceinline__ uint32_t pack2h(__half a, __half b) {
    return (uint32_t)__half_as_ushort(a) | ((uint32_t)__half_as_ushort(b) << 16);
}
__device__ __forceinline__ uint2 cvt4h(float4 v) {
    return make_uint2(pack2h(__float2half_rn(v.x), __float2half_rn(v.y)),
                      pack2h(__float2half_rn(v.z), __float2half_rn(v.w)));
}
__device__ __forceinline__ uint32_t cvt2h(float x, float y) {
    return pack2h(__float2half_rn(x), __float2half_rn(y));
}

// =================================================================
// Kernel 0: fused fp32 -> fp16 preconversion (all 6 arrays, single).
// =================================================================
#define XB (NTOT / 1024)   // 4096
#define WB (WTOT / 1024)   // 1024

__global__ __launch_bounds__(256) void convert_all_kernel(
    const float* __restrict__ Xq, const float* __restrict__ Xk, const float* __restrict__ Xv,
    const float* __restrict__ Wq, const float* __restrict__ Wk, const float* __restrict__ Wv)
{
    int bid = blockIdx.x;
    const float* src;
    __half* dst;
    int off;
    if (bid < 3 * XB) {
        int job = bid / XB;
        off = (bid % XB) * 256 + threadIdx.x;
        src = (job == 0) ? Xq : (job == 1) ? Xk : Xv;
        dst = g_X[job];
    } else {
        int r = bid - 3 * XB;
        int job = r / WB;
        off = (r % WB) * 256 + threadIdx.x;
        src = (job == 0) ? Wq : (job == 1) ? Wk : Wv;
        dst = g_W[job];
    }
    float4 v = ((const float4*)src)[off];
    ((uint2*)dst)[off] = cvt4h(v);
}

// =================================================================
// Kernel 1: QKV projections, mma.sync fp16 single, cp.async 2-stage,
// issue-before-wait (R6 discipline).
// CTA tile 128x128, BK=32, 8 warps (2x4), warp tile 64x32.
// =================================================================
#define PA 40      // A pitch (fp16): 80 B rows
#define PB 136     // B pitch (fp16): 272 B rows
#define PRJ_A 0
#define PRJ_B 10240
#define PRJ_STAGE 18944
#define PRJ_SMEM (2 * PRJ_STAGE)   // 37888

__global__ __launch_bounds__(256, 2) void proj_mma_kernel()
{
    const int z = blockIdx.z;
    const __half* X = g_X[z];
    const __half* W = g_W[z];
    __half* P = g_P[z];

    extern __shared__ char smem[];
    const uint32_t sb = smem_u32(smem);

    const int tid  = threadIdx.x;
    const int lane = tid & 31;
    const int wid  = tid >> 5;
    const int wm   = (wid >> 2) * 64;
    const int wn   = (wid & 3) * 32;
    const int rowBase = blockIdx.y * 128;
    const int colBase = blockIdx.x * 128;
    const int arow = lane & 15;
    const int acol = (lane >> 4) * 8;

    auto issue = [&](int it) {
        const uint32_t stb = sb + (uint32_t)(it & 1) * PRJ_STAGE;
        const int k0 = it * 32;
#pragma unroll
        for (int i = 0; i < 4; i++) {
            int idx = i * 256 + tid;           // 0..1023
            if (idx < 512) {                   // A: 128 rows x 32 k
                int r = idx >> 2, g = idx & 3;
                const __half* src = X + (size_t)(rowBase + r) * DMODEL + k0 + g * 8;
                CP16(stb + PRJ_A + r * 80 + g * 16, src);
            } else {                           // B: 32 k-rows x 128 n
                int j = idx - 512;
                int r = j >> 4, cc = j & 15;
                const __half* src = W + (size_t)(k0 + r) * DMODEL + colBase + cc * 8;
                CP16(stb + PRJ_B + r * 272 + cc * 16, src);
            }
        }
        CP_COMMIT();
    };

    float acc[4][4][4];
#pragma unroll
    for (int i = 0; i < 4; i++)
#pragma unroll
        for (int j = 0; j < 4; j++)
#pragma unroll
            for (int u = 0; u < 4; u++) acc[i][j][u] = 0.0f;

    issue(0);

    for (int it = 0; it < 32; ++it) {
        if (it < 31) issue(it + 1);
        if (it < 31) { CP_WAIT(1); } else { CP_WAIT(0); }
        __syncthreads();

        const uint32_t stb = sb + (uint32_t)(it & 1) * PRJ_STAGE;
#pragma unroll
        for (int kb = 0; kb < 32; kb += 16) {
            uint32_t ah[4][4];
#pragma unroll
            for (int mb = 0; mb < 4; mb++) {
                uint32_t off = (uint32_t)((wm + mb * 16 + arow) * PA + kb + acol) * 2;
                ldsm_x4(ah[mb], stb + PRJ_A + off);
            }
            uint32_t bh[2][4];
#pragma unroll
            for (int nb2 = 0; nb2 < 2; nb2++) {
                uint32_t off = (uint32_t)((kb + arow) * PB + wn + nb2 * 16 + acol) * 2;
                ldsm_x4t(bh[nb2], stb + PRJ_B + off);
            }
#pragma unroll
            for (int mb = 0; mb < 4; mb++)
#pragma unroll
                for (int nb = 0; nb < 4; nb++) {
                    const uint32_t* ph = &bh[nb >> 1][(nb & 1) * 2];
                    mma_fp16(acc[mb][nb], ah[mb], ph);
                }
        }
        __syncthreads();
    }

    // epilogue: fp32 acc -> fp16 store
    const int grp = lane >> 2;
    const int qd  = lane & 3;
#pragma unroll
    for (int mb = 0; mb < 4; mb++) {
#pragma unroll
        for (int nb = 0; nb < 4; nb++) {
            size_t row = (size_t)(rowBase + wm + mb * 16 + grp);
            size_t col = (size_t)(colBase + wn + nb * 8 + qd * 2);
            *(uint32_t*)&P[row * DMODEL + col] =
                cvt2h(acc[mb][nb][0], acc[mb][nb][1]);
            *(uint32_t*)&P[(row + 8) * DMODEL + col] =
                cvt2h(acc[mb][nb][2], acc[mb][nb][3]);
        }
    }
}

// =================================================================
// Kernel 2: flash attention, mma.sync fp16 single.
// CTA = (64 queries, head h, batch b); 4 warps x 16 query rows.
// K/V tiles cp.async double-buffered (R6 pipeline).
// =================================================================
#define ATP 72              // smem pitch (fp16): 144 B rows
#define AT_K 0
#define AT_V 9216
#define AT_STAGE 18432
#define AT_KM (2 * AT_STAGE)           // int[2][64] at byte 36864
#define AT_SMEM (AT_KM + 2 * 64 * 4)   // 37376

__global__ __launch_bounds__(128) void attn_mma_kernel(
    const int* __restrict__ qmask, const int* __restrict__ kmask)
{
    extern __shared__ char smem[];
    const uint32_t sb = smem_u32(smem);
    int* sKm = (int*)(smem + AT_KM);

    const int tid  = threadIdx.x;
    const int lane = tid & 31;
    const int wid  = tid >> 5;
    const int grp  = lane >> 2;
    const int qc   = lane & 3;
    const int arow = lane & 15;
    const int acol = (lane >> 4) * 8;

    const int q0 = blockIdx.x * 64;
    const int h  = blockIdx.y;
    const int b  = blockIdx.z;
    const size_t rowB = (size_t)b * SEQ;
    const size_t hoff = (size_t)h * HDIM;

    const __half* Q = g_P[0];
    const __half* K = g_P[1];
    const __half* V = g_P[2];

    auto issue = [&](int it) {
        const int s = it & 1;
        const int k0 = it * 64;
        const uint32_t stb = sb + (uint32_t)s * AT_STAGE;
#pragma unroll
        for (int i = 0; i < 8; i++) {
            int idx = i * 128 + tid;          // 0..1023
            int arr = idx >> 9;               // 0 = K, 1 = V
            int rem = idx & 511;
            int r = rem >> 3, cc = rem & 7;
            const __half* base = arr ? V : K;
            const __half* src = base + (rowB + k0 + r) * DMODEL + hoff + cc * 8;
            CP16(stb + (uint32_t)arr * 9216 + r * 144 + cc * 16, src);
        }
        if (tid < 64) sKm[s * 64 + tid] = kmask[rowB + k0 + tid];
        CP_COMMIT();
    };

    issue(0);

    // ---- Q fragments straight from global, register-resident ----
    const int gq0 = q0 + wid * 16 + grp;      // global query row (and +8)
    uint32_t qf[4][4];
    {
        const size_t r0 = (rowB + gq0) * DMODEL + hoff + 2 * qc;
#pragma unroll
        for (int kb = 0; kb < 4; kb++) {
            size_t base = r0 + kb * 16;
            qf[kb][0] = *(const uint32_t*)&Q[base];
            qf[kb][1] = *(const uint32_t*)&Q[base + 8 * DMODEL];
            qf[kb][2] = *(const uint32_t*)&Q[base + 8];
            qf[kb][3] = *(const uint32_t*)&Q[base + 8 * DMODEL + 8];
        }
    }

    float out[8][4];
#pragma unroll
    for (int nb = 0; nb < 8; nb++)
#pragma unroll
        for (int u = 0; u < 4; u++) out[nb][u] = 0.0f;
    float m0 = -1e30f, m1 = -1e30f, l0 = 0.0f, l1 = 0.0f;

    for (int it = 0; it < SEQ / 64; ++it) {
        if (it < 15) issue(it + 1);
        if (it < 15) { CP_WAIT(1); } else { CP_WAIT(0); }
        __syncthreads();

        const int s = it & 1;
        const uint32_t stb = sb + (uint32_t)s * AT_STAGE;
        const int* km = &sKm[s * 64];

        // ---- scores S = Q K^T ----
        float sc[8][4];
#pragma unroll
        for (int nb = 0; nb < 8; nb++)
#pragma unroll
            for (int u = 0; u < 4; u++) sc[nb][u] = 0.0f;

#pragma unroll
        for (int kb = 0; kb < 4; kb++) {
            uint32_t bk[4][4];
#pragma unroll
            for (int nb2 = 0; nb2 < 4; nb2++) {
                uint32_t off = (uint32_t)((nb2 * 16 + arow) * ATP + kb * 16 + acol) * 2;
                ldsm_x4(bk[nb2], stb + AT_K + off);
            }
#pragma unroll
            for (int nb = 0; nb < 8; nb++) {
                int g2 = nb >> 1, sub = nb & 1;
                uint32_t bh[2] = {bk[g2][sub], bk[g2][sub + 2]};
                mma_fp16(sc[nb], qf[kb], bh);
            }
        }

        // ---- scale + key mask ----
#pragma unroll
        for (int nb = 0; nb < 8; nb++) {
            int c0 = nb * 8 + 2 * qc;
            int k0m = km[c0], k1m = km[c0 + 1];
            sc[nb][0] = k0m ? sc[nb][0] * 0.125f : PADV;
            sc[nb][1] = k1m ? sc[nb][1] * 0.125f : PADV;
            sc[nb][2] = k0m ? sc[nb][2] * 0.125f : PADV;
            sc[nb][3] = k1m ? sc[nb][3] * 0.125f : PADV;
        }

        // ---- online softmax (rows gq0 and gq0+8) ----
        float mx0 = -1e30f, mx1 = -1e30f;
#pragma unroll
        for (int nb = 0; nb < 8; nb++) {
            mx0 = fmaxf(mx0, fmaxf(sc[nb][0], sc[nb][1]));
            mx1 = fmaxf(mx1, fmaxf(sc[nb][2], sc[nb][3]));
        }
        mx0 = fmaxf(mx0, __shfl_xor_sync(0xffffffffu, mx0, 1));
        mx0 = fmaxf(mx0, __shfl_xor_sync(0xffffffffu, mx0, 2));
        mx1 = fmaxf(mx1, __shfl_xor_sync(0xffffffffu, mx1, 1));
        mx1 = fmaxf(mx1, __shfl_xor_sync(0xffffffffu, mx1, 2));
        float mn0 = fmaxf(m0, mx0), mn1 = fmaxf(m1, mx1);
        float a0 = __expf(m0 - mn0), a1 = __expf(m1 - mn1);
        float rs0 = 0.0f, rs1 = 0.0f;
#pragma unroll
        for (int nb = 0; nb < 8; nb++) {
            sc[nb][0] = __expf(sc[nb][0] - mn0); rs0 += sc[nb][0];
            sc[nb][1] = __expf(sc[nb][1] - mn0); rs0 += sc[nb][1];
            sc[nb][2] = __expf(sc[nb][2] - mn1); rs1 += sc[nb][2];
            sc[nb][3] = __expf(sc[nb][3] - mn1); rs1 += sc[nb][3];
        }
        rs0 += __shfl_xor_sync(0xffffffffu, rs0, 1);
        rs0 += __shfl_xor_sync(0xffffffffu, rs0, 2);
        rs1 += __shfl_xor_sync(0xffffffffu, rs1, 1);
        rs1 += __shfl_xor_sync(0xffffffffu, rs1, 2);
        l0 = l0 * a0 + rs0;
        l1 = l1 * a1 + rs1;
        m0 = mn0;
        m1 = mn1;
#pragma unroll
        for (int nb = 0; nb < 8; nb++) {
            out[nb][0] *= a0; out[nb][1] *= a0;
            out[nb][2] *= a1; out[nb][3] *= a1;
        }

        // ---- O += P V ----
#pragma unroll
        for (int kb = 0; kb < 4; kb++) {
            uint32_t pa[4];
            pa[0] = cvt2h(sc[2 * kb][0],     sc[2 * kb][1]);
            pa[1] = cvt2h(sc[2 * kb][2],     sc[2 * kb][3]);
            pa[2] = cvt2h(sc[2 * kb + 1][0], sc[2 * kb + 1][1]);
            pa[3] = cvt2h(sc[2 * kb + 1][2], sc[2 * kb + 1][3]);

            uint32_t bv[4][4];
#pragma unroll
            for (int nb2 = 0; nb2 < 4; nb2++) {
                uint32_t off = (uint32_t)((kb * 16 + arow) * ATP + nb2 * 16 + acol) * 2;
                ldsm_x4t(bv[nb2], stb + AT_V + off);
            }
#pragma unroll
            for (int nb = 0; nb < 8; nb++) {
                int g2 = nb >> 1, sub = nb & 1;
                const uint32_t* bh = &bv[g2][2 * sub];
                mma_fp16(out[nb], pa, bh);
            }
        }
        __syncthreads();
    }

    // ---- finalize: 1/l, query mask, fp32 store ----
    float s0 = (float)qmask[rowB + gq0]     / l0;
    float s1 = (float)qmask[rowB + gq0 + 8] / l1;
#pragma unroll
    for (int nb = 0; nb < 8; nb++) {
        size_t col = hoff + nb * 8 + 2 * qc;
        *(float2*)&g_O[(rowB + gq0) * DMODEL + col] =
            make_float2(out[nb][0] * s0, out[nb][1] * s0);
        *(float2*)&g_O[(rowB + gq0 + 8) * DMODEL + col] =
            make_float2(out[nb][2] * s1, out[nb][3] * s1);
    }
}

// =================================================================
// Kernel 3: residual + LayerNorm per row (unchanged)
// =================================================================
__device__ __forceinline__ float block_sum256(float v, float* red)
{
#pragma unroll
    for (int off = 16; off; off >>= 1)
        v += __shfl_xor_sync(0xffffffffu, v, off);
    if ((threadIdx.x & 31) == 0) red[threadIdx.x >> 5] = v;
    __syncthreads();
    float tot = 0.0f;
#pragma unroll
    for (int w = 0; w < 8; w++) tot += red[w];
    __syncthreads();
    return tot;
}

__global__ __launch_bounds__(256) void ln_kernel(
    const float* __restrict__ queries,
    const float* __restrict__ gamma,
    const float* __restrict__ beta,
    float* __restrict__ out)
{
    __shared__ float red[8];
    const int row = blockIdx.x;
    const int t   = threadIdx.x;
    const size_t base = (size_t)row * DMODEL + t * 4;

    float4 a = *(const float4*)&queries[base];
    float4 b = *(const float4*)&g_O[base];
    float x[4] = {a.x + b.x, a.y + b.y, a.z + b.z, a.w + b.w};

    float s = x[0] + x[1] + x[2] + x[3];
    s = block_sum256(s, red);
    float mean = s * (1.0f / DMODEL);

    float d[4] = {x[0] - mean, x[1] - mean, x[2] - mean, x[3] - mean};
    float ss = d[0] * d[0] + d[1] * d[1] + d[2] * d[2] + d[3] * d[3];
    ss = block_sum256(ss, red);
    float rstd = rsqrtf(ss * (1.0f / DMODEL) + LNEPS);

    float4 g  = *(const float4*)&gamma[t * 4];
    float4 be = *(const float4*)&beta[t * 4];
    float4 y = make_float4(g.x * d[0] * rstd + be.x,
                           g.y * d[1] * rstd + be.y,
                           g.z * d[2] * rstd + be.z,
                           g.w * d[3] * rstd + be.w);
    *(float4*)&out[base] = y;
}

// =================================================================
extern "C" void kernel_launch(void* const* d_in, const int* in_sizes, int n_in,
                              void* d_out, int out_size)
{
    const float* queries = (const float*)d_in[0];
    const float* keys    = (const float*)d_in[1];
    const float* values  = (const float*)d_in[2];
    const int*   qmask   = (const int*)d_in[3];
    const int*   kmask   = (const int*)d_in[4];
    const float* Wq      = (const float*)d_in[5];
    const float* Wk      = (const float*)d_in[6];
    const float* Wv      = (const float*)d_in[7];
    const float* gamma   = (const float*)d_in[8];
    const float* beta    = (const float*)d_in[9];
    float* out = (float*)d_out;

    cudaFuncSetAttribute(proj_mma_kernel,
                         cudaFuncAttributeMaxDynamicSharedMemorySize, PRJ_SMEM);
    cudaFuncSetAttribute(attn_mma_kernel,
                         cudaFuncAttributeMaxDynamicSharedMemorySize, AT_SMEM);

    convert_all_kernel<<<3 * XB + 3 * WB, 256>>>(queries, keys, values, Wq, Wk, Wv);

    proj_mma_kernel<<<dim3(DMODEL / 128, (BATCH * SEQ) / 128, 3), 256, PRJ_SMEM>>>();

    attn_mma_kernel<<<dim3(SEQ / 64, NHEAD, BATCH), 128, AT_SMEM>>>(qmask, kmask);

    ln_kernel<<<BATCH * SEQ, 256>>>(queries, gamma, beta, out);
}

// round 12
// speedup vs baseline: 2.5604x; 1.0308x over previous
#include <cuda_runtime.h>
#include <cuda_fp16.h>
#include <cstdint>

#define BATCH 4
#define SEQ   1024
#define DMODEL 1024
#define NHEAD 16
#define HDIM  64
#define PADV  (-1e7f)
#define LNEPS 1e-3f
#define NTOT  (BATCH*SEQ*DMODEL)   // 4194304
#define WTOT  (DMODEL*DMODEL)      // 1048576

// ---------------- scratch (device globals; no allocations) ----------------
__device__ __half g_X[3][NTOT];    // fp16 inputs (q,k,v)
__device__ __half g_W[3][WTOT];    // fp16 weights
__device__ __half g_P[3][NTOT];    // projected Q,K,V (fp16)
__device__ float  g_O[NTOT];       // attention output (fp32)

// =================================================================
// helpers
// =================================================================
__device__ __forceinline__ uint32_t smem_u32(const void* p) {
    uint32_t a;
    asm("{ .reg .u64 t; cvta.to.shared.u64 t, %1; cvt.u32.u64 %0, t; }"
        : "=r"(a) : "l"(p));
    return a;
}

__device__ __forceinline__ void ldsm_x4(uint32_t* r, uint32_t addr) {
    asm volatile("ldmatrix.sync.aligned.m8n8.x4.shared.b16 {%0,%1,%2,%3}, [%4];"
                 : "=r"(r[0]), "=r"(r[1]), "=r"(r[2]), "=r"(r[3]) : "r"(addr));
}
__device__ __forceinline__ void ldsm_x4t(uint32_t* r, uint32_t addr) {
    asm volatile("ldmatrix.sync.aligned.m8n8.x4.trans.shared.b16 {%0,%1,%2,%3}, [%4];"
                 : "=r"(r[0]), "=r"(r[1]), "=r"(r[2]), "=r"(r[3]) : "r"(addr));
}
__device__ __forceinline__ void mma_fp16(float* d, const uint32_t* a, const uint32_t* b) {
    asm volatile(
        "mma.sync.aligned.m16n8k16.row.col.f32.f16.f16.f32 "
        "{%0,%1,%2,%3}, {%4,%5,%6,%7}, {%8,%9}, {%0,%1,%2,%3};"
        : "+f"(d[0]), "+f"(d[1]), "+f"(d[2]), "+f"(d[3])
        : "r"(a[0]), "r"(a[1]), "r"(a[2]), "r"(a[3]), "r"(b[0]), "r"(b[1]));
}

#define CP16(dst, src) \
    asm volatile("cp.async.cg.shared.global [%0], [%1], 16;" :: "r"(dst), "l"(src))
#define CP_COMMIT() asm volatile("cp.async.commit_group;" ::: "memory")
#define CP_WAIT(n)  asm volatile("cp.async.wait_group %0;" :: "n"(n) : "memory")

__device__ __forceinline__ uint32_t pack2h(__half a, __half b) {
    return (uint32_t)__half_as_ushort(a) | ((uint32_t)__half_as_ushort(b) << 16);
}
__device__ __forceinline__ uint2 cvt4h(float4 v) {
    return make_uint2(pack2h(__float2half_rn(v.x), __float2half_rn(v.y)),
                      pack2h(__float2half_rn(v.z), __float2half_rn(v.w)));
}
__device__ __forceinline__ uint32_t cvt2h(float x, float y) {
    return pack2h(__float2half_rn(x), __float2half_rn(y));
}

// =================================================================
// Kernel 0: fused fp32 -> fp16 preconversion (all 6 arrays).
// =================================================================
#define XB (NTOT / 1024)   // 4096
#define WB (WTOT / 1024)   // 1024

__global__ __launch_bounds__(256) void convert_all_kernel(
    const float* __restrict__ Xq, const float* __restrict__ Xk, const float* __restrict__ Xv,
    const float* __restrict__ Wq, const float* __restrict__ Wk, const float* __restrict__ Wv)
{
    int bid = blockIdx.x;
    const float* src;
    __half* dst;
    int off;
    if (bid < 3 * XB) {
        int job = bid / XB;
        off = (bid % XB) * 256 + threadIdx.x;
        src = (job == 0) ? Xq : (job == 1) ? Xk : Xv;
        dst = g_X[job];
    } else {
        int r = bid - 3 * XB;
        int job = r / WB;
        off = (r % WB) * 256 + threadIdx.x;
        src = (job == 0) ? Wq : (job == 1) ? Wk : Wv;
        dst = g_W[job];
    }
    float4 v = ((const float4*)src)[off];
    ((uint2*)dst)[off] = cvt4h(v);
}

// =================================================================
// Kernel 1: QKV projections, mma.sync fp16 single, cp.async 2-stage,
// issue-before-wait, BK=64 (16 iterations).
// CTA tile 128x128, 8 warps (2x4), warp tile 64x32.
// =================================================================
#define PA 72      // A pitch (fp16): 144 B rows (9x16B units, odd -> conflict-free)
#define PB 136     // B pitch (fp16): 272 B rows
#define PRJ_A 0
#define PRJ_B 18432                 // 128*144
#define PRJ_STAGE (18432 + 17408)   // + 64*272 = 35840
#define PRJ_SMEM (2 * PRJ_STAGE)    // 71680

__global__ __launch_bounds__(256, 2) void proj_mma_kernel()
{
    const int z = blockIdx.z;
    const __half* X = g_X[z];
    const __half* W = g_W[z];
    __half* P = g_P[z];

    extern __shared__ char smem[];
    const uint32_t sb = smem_u32(smem);

    const int tid  = threadIdx.x;
    const int lane = tid & 31;
    const int wid  = tid >> 5;
    const int wm   = (wid >> 2) * 64;
    const int wn   = (wid & 3) * 32;
    const int rowBase = blockIdx.y * 128;
    const int colBase = blockIdx.x * 128;
    const int arow = lane & 15;
    const int acol = (lane >> 4) * 8;

    auto issue = [&](int it) {
        const uint32_t stb = sb + (uint32_t)(it & 1) * PRJ_STAGE;
        const int k0 = it * 64;
#pragma unroll
        for (int i = 0; i < 8; i++) {
            int idx = i * 256 + tid;           // 0..2047
            if (idx < 1024) {                  // A: 128 rows x 64 k
                int r = idx >> 3, g = idx & 7;
                const __half* src = X + (size_t)(rowBase + r) * DMODEL + k0 + g * 8;
                CP16(stb + PRJ_A + r * 144 + g * 16, src);
            } else {                           // B: 64 k-rows x 128 n
                int j = idx - 1024;
                int r = j >> 4, cc = j & 15;
                const __half* src = W + (size_t)(k0 + r) * DMODEL + colBase + cc * 8;
                CP16(stb + PRJ_B + r * 272 + cc * 16, src);
            }
        }
        CP_COMMIT();
    };

    float acc[4][4][4];
#pragma unroll
    for (int i = 0; i < 4; i++)
#pragma unroll
        for (int j = 0; j < 4; j++)
#pragma unroll
            for (int u = 0; u < 4; u++) acc[i][j][u] = 0.0f;

    issue(0);

    for (int it = 0; it < 16; ++it) {
        if (it < 15) issue(it + 1);
        if (it < 15) { CP_WAIT(1); } else { CP_WAIT(0); }
        __syncthreads();

        const uint32_t stb = sb + (uint32_t)(it & 1) * PRJ_STAGE;
#pragma unroll
        for (int kb = 0; kb < 64; kb += 16) {
            uint32_t ah[4][4];
#pragma unroll
            for (int mb = 0; mb < 4; mb++) {
                uint32_t off = (uint32_t)((wm + mb * 16 + arow) * PA + kb + acol) * 2;
                ldsm_x4(ah[mb], stb + PRJ_A + off);
            }
            uint32_t bh[2][4];
#pragma unroll
            for (int nb2 = 0; nb2 < 2; nb2++) {
                uint32_t off = (uint32_t)((kb + arow) * PB + wn + nb2 * 16 + acol) * 2;
                ldsm_x4t(bh[nb2], stb + PRJ_B + off);
            }
#pragma unroll
            for (int mb = 0; mb < 4; mb++)
#pragma unroll
                for (int nb = 0; nb < 4; nb++) {
                    const uint32_t* ph = &bh[nb >> 1][(nb & 1) * 2];
                    mma_fp16(acc[mb][nb], ah[mb], ph);
                }
        }
        __syncthreads();
    }

    // epilogue: fp32 acc -> fp16 store
    const int grp = lane >> 2;
    const int qd  = lane & 3;
#pragma unroll
    for (int mb = 0; mb < 4; mb++) {
#pragma unroll
        for (int nb = 0; nb < 4; nb++) {
            size_t row = (size_t)(rowBase + wm + mb * 16 + grp);
            size_t col = (size_t)(colBase + wn + nb * 8 + qd * 2);
            *(uint32_t*)&P[row * DMODEL + col] =
                cvt2h(acc[mb][nb][0], acc[mb][nb][1]);
            *(uint32_t*)&P[(row + 8) * DMODEL + col] =
                cvt2h(acc[mb][nb][2], acc[mb][nb][3]);
        }
    }
}

// =================================================================
// Kernel 2: flash attention, mma.sync fp16 single.  (unchanged R11)
// CTA = (64 queries, head h, batch b); 4 warps x 16 query rows.
// =================================================================
#define ATP 72              // smem pitch (fp16): 144 B rows
#define AT_K 0
#define AT_V 9216
#define AT_STAGE 18432
#define AT_KM (2 * AT_STAGE)           // int[2][64] at byte 36864
#define AT_SMEM (AT_KM + 2 * 64 * 4)   // 37376

__global__ __launch_bounds__(128) void attn_mma_kernel(
    const int* __restrict__ qmask, const int* __restrict__ kmask)
{
    extern __shared__ char smem[];
    const uint32_t sb = smem_u32(smem);
    int* sKm = (int*)(smem + AT_KM);

    const int tid  = threadIdx.x;
    const int lane = tid & 31;
    const int wid  = tid >> 5;
    const int grp  = lane >> 2;
    const int qc   = lane & 3;
    const int arow = lane & 15;
    const int acol = (lane >> 4) * 8;

    const int q0 = blockIdx.x * 64;
    const int h  = blockIdx.y;
    const int b  = blockIdx.z;
    const size_t rowB = (size_t)b * SEQ;
    const size_t hoff = (size_t)h * HDIM;

    const __half* Q = g_P[0];
    const __half* K = g_P[1];
    const __half* V = g_P[2];

    auto issue = [&](int it) {
        const int s = it & 1;
        const int k0 = it * 64;
        const uint32_t stb = sb + (uint32_t)s * AT_STAGE;
#pragma unroll
        for (int i = 0; i < 8; i++) {
            int idx = i * 128 + tid;          // 0..1023
            int arr = idx >> 9;               // 0 = K, 1 = V
            int rem = idx & 511;
            int r = rem >> 3, cc = rem & 7;
            const __half* base = arr ? V : K;
            const __half* src = base + (rowB + k0 + r) * DMODEL + hoff + cc * 8;
            CP16(stb + (uint32_t)arr * 9216 + r * 144 + cc * 16, src);
        }
        if (tid < 64) sKm[s * 64 + tid] = kmask[rowB + k0 + tid];
        CP_COMMIT();
    };

    issue(0);

    // ---- Q fragments straight from global, register-resident ----
    const int gq0 = q0 + wid * 16 + grp;      // global query row (and +8)
    uint32_t qf[4][4];
    {
        const size_t r0 = (rowB + gq0) * DMODEL + hoff + 2 * qc;
#pragma unroll
        for (int kb = 0; kb < 4; kb++) {
            size_t base = r0 + kb * 16;
            qf[kb][0] = *(const uint32_t*)&Q[base];
            qf[kb][1] = *(const uint32_t*)&Q[base + 8 * DMODEL];
            qf[kb][2] = *(const uint32_t*)&Q[base + 8];
            qf[kb][3] = *(const uint32_t*)&Q[base + 8 * DMODEL + 8];
        }
    }

    float out[8][4];
#pragma unroll
    for (int nb = 0; nb < 8; nb++)
#pragma unroll
        for (int u = 0; u < 4; u++) out[nb][u] = 0.0f;
    float m0 = -1e30f, m1 = -1e30f, l0 = 0.0f, l1 = 0.0f;

    for (int it = 0; it < SEQ / 64; ++it) {
        if (it < 15) issue(it + 1);
        if (it < 15) { CP_WAIT(1); } else { CP_WAIT(0); }
        __syncthreads();

        const int s = it & 1;
        const uint32_t stb = sb + (uint32_t)s * AT_STAGE;
        const int* km = &sKm[s * 64];

        // ---- scores S = Q K^T ----
        float sc[8][4];
#pragma unroll
        for (int nb = 0; nb < 8; nb++)
#pragma unroll
            for (int u = 0; u < 4; u++) sc[nb][u] = 0.0f;

#pragma unroll
        for (int kb = 0; kb < 4; kb++) {
            uint32_t bk[4][4];
#pragma unroll
            for (int nb2 = 0; nb2 < 4; nb2++) {
                uint32_t off = (uint32_t)((nb2 * 16 + arow) * ATP + kb * 16 + acol) * 2;
                ldsm_x4(bk[nb2], stb + AT_K + off);
            }
#pragma unroll
            for (int nb = 0; nb < 8; nb++) {
                int g2 = nb >> 1, sub = nb & 1;
                uint32_t bh[2] = {bk[g2][sub], bk[g2][sub + 2]};
                mma_fp16(sc[nb], qf[kb], bh);
            }
        }

        // ---- scale + key mask ----
#pragma unroll
        for (int nb = 0; nb < 8; nb++) {
            int c0 = nb * 8 + 2 * qc;
            int k0m = km[c0], k1m = km[c0 + 1];
            sc[nb][0] = k0m ? sc[nb][0] * 0.125f : PADV;
            sc[nb][1] = k1m ? sc[nb][1] * 0.125f : PADV;
            sc[nb][2] = k0m ? sc[nb][2] * 0.125f : PADV;
            sc[nb][3] = k1m ? sc[nb][3] * 0.125f : PADV;
        }

        // ---- online softmax (rows gq0 and gq0+8) ----
        float mx0 = -1e30f, mx1 = -1e30f;
#pragma unroll
        for (int nb = 0; nb < 8; nb++) {
            mx0 = fmaxf(mx0, fmaxf(sc[nb][0], sc[nb][1]));
            mx1 = fmaxf(mx1, fmaxf(sc[nb][2], sc[nb][3]));
        }
        mx0 = fmaxf(mx0, __shfl_xor_sync(0xffffffffu, mx0, 1));
        mx0 = fmaxf(mx0, __shfl_xor_sync(0xffffffffu, mx0, 2));
        mx1 = fmaxf(mx1, __shfl_xor_sync(0xffffffffu, mx1, 1));
        mx1 = fmaxf(mx1, __shfl_xor_sync(0xffffffffu, mx1, 2));
        float mn0 = fmaxf(m0, mx0), mn1 = fmaxf(m1, mx1);
        float a0 = __expf(m0 - mn0), a1 = __expf(m1 - mn1);
        float rs0 = 0.0f, rs1 = 0.0f;
#pragma unroll
        for (int nb = 0; nb < 8; nb++) {
            sc[nb][0] = __expf(sc[nb][0] - mn0); rs0 += sc[nb][0];
            sc[nb][1] = __expf(sc[nb][1] - mn0); rs0 += sc[nb][1];
            sc[nb][2] = __expf(sc[nb][2] - mn1); rs1 += sc[nb][2];
            sc[nb][3] = __expf(sc[nb][3] - mn1); rs1 += sc[nb][3];
        }
        rs0 += __shfl_xor_sync(0xffffffffu, rs0, 1);
        rs0 += __shfl_xor_sync(0xffffffffu, rs0, 2);
        rs1 += __shfl_xor_sync(0xffffffffu, rs1, 1);
        rs1 += __shfl_xor_sync(0xffffffffu, rs1, 2);
        l0 = l0 * a0 + rs0;
        l1 = l1 * a1 + rs1;
        m0 = mn0;
        m1 = mn1;
#pragma unroll
        for (int nb = 0; nb < 8; nb++) {
            out[nb][0] *= a0; out[nb][1] *= a0;
            out[nb][2] *= a1; out[nb][3] *= a1;
        }

        // ---- O += P V ----
#pragma unroll
        for (int kb = 0; kb < 4; kb++) {
            uint32_t pa[4];
            pa[0] = cvt2h(sc[2 * kb][0],     sc[2 * kb][1]);
            pa[1] = cvt2h(sc[2 * kb][2],     sc[2 * kb][3]);
            pa[2] = cvt2h(sc[2 * kb + 1][0], sc[2 * kb + 1][1]);
            pa[3] = cvt2h(sc[2 * kb + 1][2], sc[2 * kb + 1][3]);

            uint32_t bv[4][4];
#pragma unroll
            for (int nb2 = 0; nb2 < 4; nb2++) {
                uint32_t off = (uint32_t)((kb * 16 + arow) * ATP + nb2 * 16 + acol) * 2;
                ldsm_x4t(bv[nb2], stb + AT_V + off);
            }
#pragma unroll
            for (int nb = 0; nb < 8; nb++) {
                int g2 = nb >> 1, sub = nb & 1;
                const uint32_t* bh = &bv[g2][2 * sub];
                mma_fp16(out[nb], pa, bh);
            }
        }
        __syncthreads();
    }

    // ---- finalize: 1/l, query mask, fp32 store ----
    float s0 = (float)qmask[rowB + gq0]     / l0;
    float s1 = (float)qmask[rowB + gq0 + 8] / l1;
#pragma unroll
    for (int nb = 0; nb < 8; nb++) {
        size_t col = hoff + nb * 8 + 2 * qc;
        *(float2*)&g_O[(rowB + gq0) * DMODEL + col] =
            make_float2(out[nb][0] * s0, out[nb][1] * s0);
        *(float2*)&g_O[(rowB + gq0 + 8) * DMODEL + col] =
            make_float2(out[nb][2] * s1, out[nb][3] * s1);
    }
}

// =================================================================
// Kernel 3: residual + LayerNorm, warp-per-row (no block barriers).
// 256 threads = 8 warps = 8 rows per CTA; lane covers 32 elements.
// =================================================================
__global__ __launch_bounds__(256) void ln_kernel(
    const float* __restrict__ queries,
    const float* __restrict__ gamma,
    const float* __restrict__ beta,
    float* __restrict__ out)
{
    const int lane = threadIdx.x & 31;
    const int row  = blockIdx.x * 8 + (threadIdx.x >> 5);
    const size_t rb = (size_t)row * DMODEL;

    float4 x[8];
#pragma unroll
    for (int i = 0; i < 8; i++) {
        size_t idx = rb + i * 128 + lane * 4;
        float4 a = *(const float4*)&queries[idx];
        float4 b = *(const float4*)&g_O[idx];
        x[i] = make_float4(a.x + b.x, a.y + b.y, a.z + b.z, a.w + b.w);
    }

    float s = 0.0f;
#pragma unroll
    for (int i = 0; i < 8; i++) s += x[i].x + x[i].y + x[i].z + x[i].w;
#pragma unroll
    for (int off = 16; off; off >>= 1)
        s += __shfl_xor_sync(0xffffffffu, s, off);
    float mean = s * (1.0f / DMODEL);

    float ss = 0.0f;
#pragma unroll
    for (int i = 0; i < 8; i++) {
        x[i].x -= mean; x[i].y -= mean; x[i].z -= mean; x[i].w -= mean;
        ss += x[i].x * x[i].x + x[i].y * x[i].y + x[i].z * x[i].z + x[i].w * x[i].w;
    }
#pragma unroll
    for (int off = 16; off; off >>= 1)
        ss += __shfl_xor_sync(0xffffffffu, ss, off);
    float rstd = rsqrtf(ss * (1.0f / DMODEL) + LNEPS);

#pragma unroll
    for (int i = 0; i < 8; i++) {
        int c = i * 128 + lane * 4;
        float4 g  = *(const float4*)&gamma[c];
        float4 be = *(const float4*)&beta[c];
        float4 y = make_float4(g.x * x[i].x * rstd + be.x,
                               g.y * x[i].y * rstd + be.y,
                               g.z * x[i].z * rstd + be.z,
                               g.w * x[i].w * rstd + be.w);
        *(float4*)&out[rb + c] = y;
    }
}

// =================================================================
extern "C" void kernel_launch(void* const* d_in, const int* in_sizes, int n_in,
                              void* d_out, int out_size)
{
    const float* queries = (const float*)d_in[0];
    const float* keys    = (const float*)d_in[1];
    const float* values  = (const float*)d_in[2];
    const int*   qmask   = (const int*)d_in[3];
    const int*   kmask   = (const int*)d_in[4];
    const float* Wq      = (const float*)d_in[5];
    const float* Wk      = (const float*)d_in[6];
    const float* Wv      = (const float*)d_in[7];
    const float* gamma   = (const float*)d_in[8];
    const float* beta    = (const float*)d_in[9];
    float* out = (float*)d_out;

    cudaFuncSetAttribute(proj_mma_kernel,
                         cudaFuncAttributeMaxDynamicSharedMemorySize, PRJ_SMEM);
    cudaFuncSetAttribute(attn_mma_kernel,
                         cudaFuncAttributeMaxDynamicSharedMemorySize, AT_SMEM);

    convert_all_kernel<<<3 * XB + 3 * WB, 256>>>(queries, keys, values, Wq, Wk, Wv);

    proj_mma_kernel<<<dim3(DMODEL / 128, (BATCH * SEQ) / 128, 3), 256, PRJ_SMEM>>>();

    attn_mma_kernel<<<dim3(SEQ / 64, NHEAD, BATCH), 128, AT_SMEM>>>(qmask, kmask);

    ln_kernel<<<(BATCH * SEQ) / 8, 256>>>(queries, gamma, beta, out);
}